// round 13
// baseline (speedup 1.0000x reference)
#include <cuda_runtime.h>
#include <math.h>
#include <stdint.h>

#define NNODES 50000
#define NEDGES 800000
#define FDIM 128
#define HDIM 128
#define ODIM 128
#define KOBS 4
#define ZDIM 512   /* K*H */
#define MID  256   /* 2*H */

// ---------------- scratch (device globals; no allocation allowed) ----------
__device__ __align__(16) float g_h  [(size_t)NNODES * HDIM];
__device__ __align__(16) float g_hw [(size_t)NNODES * HDIM];
__device__ __align__(16) float g_agg[(size_t)NNODES * ZDIM];
__device__ __align__(16) float g_z1 [(size_t)NNODES * MID];
__device__ double g_colsum  [ZDIM];
__device__ double g_colsumsq[ZDIM];
__device__ __align__(16) float g_scale[ZDIM];   // bn scale * attention
__device__ __align__(16) float g_shift[ZDIM];   // bn shift * attention
__device__ unsigned int g_distmax_bits;
// CSR structures
__device__ int g_cnt[NNODES];
__device__ int g_off[NNODES + 1];
__device__ int g_cur[NNODES];
__device__ int g_esrc[NEDGES];
__device__ __align__(16) float4 g_eab[NEDGES];

__device__ __forceinline__ float to_tf32(float x) {
    float r;
    asm("cvt.rna.tf32.f32 %0, %1;" : "=f"(r) : "f"(x));
    return r;
}

// ---------------- zero / init ----------------------------------------------
__global__ void k_zero_misc() {
    int i = blockIdx.x * blockDim.x + threadIdx.x;
    if (i == 0) g_distmax_bits = 0u;
    if (i < ZDIM) { g_colsum[i] = 0.0; g_colsumsq[i] = 0.0; }
    for (; i < NNODES; i += gridDim.x * blockDim.x) g_cnt[i] = 0;
}

// ---------------- tf32 tensor GEMM, cp.async 2-stage, 2 CTA/SM --------------
// C[r,c] = sum_k A[r,k] * W[c,k] + bias[c]   (A @ W^T + b)
// Raw fp32 inputs; tiles are tf32-rounded IN SMEM after cp.async lands.
// amode==1: A additionally transformed: relu(a*g_scale[k]+g_shift[k]).
// 512 threads, tile 128x128, BK=32, 16 warps x (32x32).
#define GSM_STAGE 9216          /* floats per stage (A 4608 + W 4608) */
#define GSMEM     73728         /* bytes */

__global__ void __launch_bounds__(512, 2)
k_gemm(const float* __restrict__ A, const float* __restrict__ W,
       const float* __restrict__ bias, float* __restrict__ C,
       int nrows, int kdim, int mcols, int do_relu, int amode)
{
    extern __shared__ float sm[];
    const int tid  = threadIdx.x;
    const int warp = tid >> 5;
    const int lane = tid & 31;
    const int row0 = blockIdx.y * 128;
    const int col0 = blockIdx.x * 128;
    const int mw = (warp & 3) * 32;
    const int nw = (warp >> 2) * 32;
    const int gq = lane >> 2;
    const int tq = lane & 3;
    const int r_ld = tid >> 3;           // 0..63
    const int kv   = (tid & 7) * 4;      // 0..28

    float acc[2][4][4];
#pragma unroll
    for (int mi = 0; mi < 2; mi++)
#pragma unroll
        for (int ni = 0; ni < 4; ni++)
#pragma unroll
            for (int q = 0; q < 4; q++) acc[mi][ni][q] = 0.f;

#define ISSUE(ST)                                                              \
    do {                                                                       \
        const int k0_ = (ST) * 32;                                             \
        float* dA_ = sm + ((ST) & 1) * GSM_STAGE;                              \
        _Pragma("unroll")                                                      \
        for (int t = 0; t < 2; t++) {                                          \
            int r = r_ld + t * 64;                                             \
            int ar = row0 + r; if (ar > nrows - 1) ar = nrows - 1;             \
            const float* sA = A + (size_t)ar * kdim + k0_ + kv;                \
            uint32_t du = (uint32_t)__cvta_generic_to_shared(dA_ + r * 36 + kv); \
            asm volatile("cp.async.cg.shared.global [%0], [%1], 16;"           \
                         :: "r"(du), "l"(sA));                                 \
            const float* sW = W + (size_t)(col0 + r) * kdim + k0_ + kv;        \
            uint32_t dw = (uint32_t)__cvta_generic_to_shared(dA_ + 4608 + r * 36 + kv); \
            asm volatile("cp.async.cg.shared.global [%0], [%1], 16;"           \
                         :: "r"(dw), "l"(sW));                                 \
        }                                                                      \
        asm volatile("cp.async.commit_group;" ::: "memory");                   \
    } while (0)

    const int nch = kdim >> 5;
    ISSUE(0);
    if (nch > 1) ISSUE(1);

    for (int i = 0; i < nch; i++) {
        if (i < nch - 1) asm volatile("cp.async.wait_group 1;" ::: "memory");
        else             asm volatile("cp.async.wait_group 0;" ::: "memory");
        __syncthreads();
        float* As = sm + (i & 1) * GSM_STAGE;
        float* Ws = As + 4608;

        // ---- in-smem transform/round of the slots this thread loaded ----
        {
            const int k0 = i * 32;
            float4 sc, sh;
            if (amode) {
                sc = *(const float4*)&g_scale[k0 + kv];
                sh = *(const float4*)&g_shift[k0 + kv];
            }
#pragma unroll
            for (int t = 0; t < 2; t++) {
                int r = r_ld + t * 64;
                float4* pa = (float4*)(As + r * 36 + kv);
                float4 v = *pa;
                if (amode) {
                    v.x = fmaxf(fmaf(v.x, sc.x, sh.x), 0.f);
                    v.y = fmaxf(fmaf(v.y, sc.y, sh.y), 0.f);
                    v.z = fmaxf(fmaf(v.z, sc.z, sh.z), 0.f);
                    v.w = fmaxf(fmaf(v.w, sc.w, sh.w), 0.f);
                }
                v.x = to_tf32(v.x); v.y = to_tf32(v.y);
                v.z = to_tf32(v.z); v.w = to_tf32(v.w);
                *pa = v;
                float4* pw = (float4*)(Ws + r * 36 + kv);
                float4 w = *pw;
                w.x = to_tf32(w.x); w.y = to_tf32(w.y);
                w.z = to_tf32(w.z); w.w = to_tf32(w.w);
                *pw = w;
            }
        }
        __syncthreads();

#pragma unroll
        for (int j = 0; j < 4; j++) {
            const int kk = j * 8;
            uint32_t af[8], bf[8];
#pragma unroll
            for (int mi = 0; mi < 2; mi++) {
                int r = mw + mi * 16 + gq;
                af[mi * 4 + 0] = __float_as_uint(As[r * 36 + kk + tq]);
                af[mi * 4 + 1] = __float_as_uint(As[(r + 8) * 36 + kk + tq]);
                af[mi * 4 + 2] = __float_as_uint(As[r * 36 + kk + tq + 4]);
                af[mi * 4 + 3] = __float_as_uint(As[(r + 8) * 36 + kk + tq + 4]);
            }
#pragma unroll
            for (int ni = 0; ni < 4; ni++) {
                int cc = nw + ni * 8 + gq;
                bf[ni * 2 + 0] = __float_as_uint(Ws[cc * 36 + kk + tq]);
                bf[ni * 2 + 1] = __float_as_uint(Ws[cc * 36 + kk + tq + 4]);
            }
#pragma unroll
            for (int mi = 0; mi < 2; mi++)
#pragma unroll
                for (int ni = 0; ni < 4; ni++) {
                    asm volatile(
                        "mma.sync.aligned.m16n8k8.row.col.f32.tf32.tf32.f32 "
                        "{%0,%1,%2,%3}, {%4,%5,%6,%7}, {%8,%9}, {%0,%1,%2,%3};"
                        : "+f"(acc[mi][ni][0]), "+f"(acc[mi][ni][1]),
                          "+f"(acc[mi][ni][2]), "+f"(acc[mi][ni][3])
                        : "r"(af[mi * 4 + 0]), "r"(af[mi * 4 + 1]),
                          "r"(af[mi * 4 + 2]), "r"(af[mi * 4 + 3]),
                          "r"(bf[ni * 2 + 0]), "r"(bf[ni * 2 + 1]));
                }
        }
        __syncthreads();
        if (i + 2 < nch) ISSUE(i + 2);
    }

    // ---- epilogue: bias (+ optional relu) ----
#pragma unroll
    for (int mi = 0; mi < 2; mi++) {
        int r0 = row0 + mw + mi * 16 + gq;
#pragma unroll
        for (int ni = 0; ni < 4; ni++) {
            int ccol = col0 + nw + ni * 8 + tq * 2;
            float b0 = bias[ccol], b1 = bias[ccol + 1];
            float v0 = acc[mi][ni][0] + b0;
            float v1 = acc[mi][ni][1] + b1;
            float v2 = acc[mi][ni][2] + b0;
            float v3 = acc[mi][ni][3] + b1;
            if (do_relu) {
                v0 = fmaxf(v0, 0.f); v1 = fmaxf(v1, 0.f);
                v2 = fmaxf(v2, 0.f); v3 = fmaxf(v3, 0.f);
            }
            if (r0 < nrows)
                *(float2*)&C[(size_t)r0 * mcols + ccol] = make_float2(v0, v1);
            if (r0 + 8 < nrows)
                *(float2*)&C[(size_t)(r0 + 8) * mcols + ccol] = make_float2(v2, v3);
        }
    }
}

// ---------------- pass 1 over edges: max distance + dst histogram -----------
__global__ void k_distmax_hist(const int* __restrict__ ei, const float* __restrict__ pos)
{
    int i = blockIdx.x * blockDim.x + threadIdx.x;
    float m = 0.f;
    for (; i < NEDGES; i += gridDim.x * blockDim.x) {
        int s = ei[i], d = ei[NEDGES + i];
        float ax = pos[3 * s + 0] - pos[3 * d + 0];
        float ay = pos[3 * s + 1] - pos[3 * d + 1];
        float az = pos[3 * s + 2] - pos[3 * d + 2];
        m = fmaxf(m, sqrtf(ax * ax + ay * ay + az * az));
        atomicAdd(&g_cnt[d], 1);
    }
#pragma unroll
    for (int o = 16; o; o >>= 1) m = fmaxf(m, __shfl_xor_sync(0xffffffffu, m, o));
    if ((threadIdx.x & 31) == 0) atomicMax(&g_distmax_bits, __float_as_uint(m));
}

// ---------------- exclusive scan of g_cnt -> g_off, g_cur (one block) -------
__global__ void __launch_bounds__(1024) k_scan()
{
    const int CH = (NNODES + 1023) / 1024;   // 49
    __shared__ int wsum[32];
    int t = threadIdx.x;
    int lane = t & 31, wid = t >> 5;
    int base = t * CH;

    int s = 0;
#pragma unroll 4
    for (int i = 0; i < CH; i++) {
        int idx = base + i;
        if (idx < NNODES) s += g_cnt[idx];
    }
    int incl = s;
#pragma unroll
    for (int o = 1; o < 32; o <<= 1) {
        int v = __shfl_up_sync(0xffffffffu, incl, o);
        if (lane >= o) incl += v;
    }
    if (lane == 31) wsum[wid] = incl;
    __syncthreads();
    if (wid == 0) {
        int w = wsum[lane];
        int wi = w;
#pragma unroll
        for (int o = 1; o < 32; o <<= 1) {
            int v = __shfl_up_sync(0xffffffffu, wi, o);
            if (lane >= o) wi += v;
        }
        wsum[lane] = wi - w;   // exclusive warp offsets
    }
    __syncthreads();
    int excl = wsum[wid] + incl - s;
    int run = excl;
    for (int i = 0; i < CH; i++) {
        int idx = base + i;
        if (idx < NNODES) {
            g_off[idx] = run;
            g_cur[idx] = run;
            run += g_cnt[idx];
        }
    }
    if (t == 1023) g_off[NNODES] = NEDGES;
}

// ---------------- pass 2: compute ab[4] per edge, place into CSR order ------
__global__ void k_reorder(const int* __restrict__ ei, const float* __restrict__ pos,
                          const float* __restrict__ vfp, const float* __restrict__ vparams)
{
    int e = blockIdx.x * blockDim.x + threadIdx.x;
    if (e >= NEDGES) return;
    int s = __ldg(&ei[e]);
    int d = __ldg(&ei[NEDGES + e]);

    float ax = pos[3 * s + 0] - pos[3 * d + 0];
    float ay = pos[3 * s + 1] - pos[3 * d + 1];
    float az = pos[3 * s + 2] - pos[3 * d + 2];
    float dist = sqrtf(ax * ax + ay * ay + az * az);
    float dmax = __uint_as_float(g_distmax_bits);
    float r    = dist / dmax;
    float inv  = 1.f / (dist + 1e-8f);
    float dsum = (ax + ay + az) * inv;
    float vf   = vfp[0];

    float4 ab;
    {
        float v, g2;
        v = vf * fminf(r, vparams[0]); g2 = 1.f - v * v + 1e-8f;
        ab.x = sqrtf(g2) / (1.f + v * dsum);
        v = vf * fminf(r, vparams[1]); g2 = 1.f - v * v + 1e-8f;
        ab.y = sqrtf(g2) / (1.f + v * dsum);
        v = vf * fminf(r, vparams[2]); g2 = 1.f - v * v + 1e-8f;
        ab.z = sqrtf(g2) / (1.f + v * dsum);
        v = vf * fminf(r, vparams[3]); g2 = 1.f - v * v + 1e-8f;
        ab.w = sqrtf(g2) / (1.f + v * dsum);
    }
    int p = atomicAdd(&g_cur[d], 1);
    g_esrc[p] = s;
    g_eab[p]  = ab;
}

// ---------------- aggregate: one warp per node + fused BN column stats ------
// Stats fusion uses a BLOCK-LEVEL smem reduction and only 1024 fp64 atomics
// per block (512 blocks -> 512 serialized ops/address, ~8us total).
#define ACCUM(AB, HV)                                                        \
    do {                                                                     \
        acc[ 0] = fmaf(AB.x, HV.x, acc[ 0]); acc[ 1] = fmaf(AB.x, HV.y, acc[ 1]); \
        acc[ 2] = fmaf(AB.x, HV.z, acc[ 2]); acc[ 3] = fmaf(AB.x, HV.w, acc[ 3]); \
        acc[ 4] = fmaf(AB.y, HV.x, acc[ 4]); acc[ 5] = fmaf(AB.y, HV.y, acc[ 5]); \
        acc[ 6] = fmaf(AB.y, HV.z, acc[ 6]); acc[ 7] = fmaf(AB.y, HV.w, acc[ 7]); \
        acc[ 8] = fmaf(AB.z, HV.x, acc[ 8]); acc[ 9] = fmaf(AB.z, HV.y, acc[ 9]); \
        acc[10] = fmaf(AB.z, HV.z, acc[10]); acc[11] = fmaf(AB.z, HV.w, acc[11]); \
        acc[12] = fmaf(AB.w, HV.x, acc[12]); acc[13] = fmaf(AB.w, HV.y, acc[13]); \
        acc[14] = fmaf(AB.w, HV.z, acc[14]); acc[15] = fmaf(AB.w, HV.w, acc[15]); \
    } while (0)

__global__ void __launch_bounds__(256)
k_agg()
{
    __shared__ float ssum[ZDIM], ssq[ZDIM];
    const int tid  = threadIdx.x;
    const int lane = tid & 31;
    const int wid  = (blockIdx.x << 3) + (tid >> 5);
    const int nwarps = gridDim.x << 3;
    const float* __restrict__ hw = g_hw;
    const int*   __restrict__ esrc = g_esrc;
    const float4* __restrict__ eab = g_eab;

    ssum[tid] = 0.f; ssum[tid + 256] = 0.f;
    ssq[tid]  = 0.f; ssq[tid + 256]  = 0.f;
    __syncthreads();

    float csum[16], csq[16];
#pragma unroll
    for (int i = 0; i < 16; i++) { csum[i] = 0.f; csq[i] = 0.f; }

    for (int node = wid; node < NNODES; node += nwarps) {
        float acc[16];
#pragma unroll
        for (int i = 0; i < 16; i++) acc[i] = 0.f;
        const int p0 = g_off[node], p1 = g_off[node + 1];
        int p = p0;
        for (; p + 4 <= p1; p += 4) {
            int s0 = esrc[p + 0], s1 = esrc[p + 1];
            int s2 = esrc[p + 2], s3 = esrc[p + 3];
            float4 ab0 = eab[p + 0], ab1 = eab[p + 1];
            float4 ab2 = eab[p + 2], ab3 = eab[p + 3];
            float4 h0 = *(const float4*)&hw[(size_t)s0 * HDIM + lane * 4];
            float4 h1 = *(const float4*)&hw[(size_t)s1 * HDIM + lane * 4];
            float4 h2 = *(const float4*)&hw[(size_t)s2 * HDIM + lane * 4];
            float4 h3 = *(const float4*)&hw[(size_t)s3 * HDIM + lane * 4];
            ACCUM(ab0, h0);
            ACCUM(ab1, h1);
            ACCUM(ab2, h2);
            ACCUM(ab3, h3);
        }
        for (; p < p1; p++) {
            int s = esrc[p];
            float4 ab = eab[p];
            float4 h = *(const float4*)&hw[(size_t)s * HDIM + lane * 4];
            ACCUM(ab, h);
        }
        float* op = &g_agg[(size_t)node * ZDIM + lane * 4];
        *(float4*)(op + 0 * HDIM) = make_float4(acc[ 0], acc[ 1], acc[ 2], acc[ 3]);
        *(float4*)(op + 1 * HDIM) = make_float4(acc[ 4], acc[ 5], acc[ 6], acc[ 7]);
        *(float4*)(op + 2 * HDIM) = make_float4(acc[ 8], acc[ 9], acc[10], acc[11]);
        *(float4*)(op + 3 * HDIM) = make_float4(acc[12], acc[13], acc[14], acc[15]);
#pragma unroll
        for (int i = 0; i < 16; i++) {
            csum[i] += acc[i];
            csq[i]   = fmaf(acc[i], acc[i], csq[i]);
        }
    }

    // block-level reduction into smem (float atomics, conflict degree 8)
#pragma unroll
    for (int i = 0; i < 16; i++) {
        int col = (i >> 2) * HDIM + lane * 4 + (i & 3);
        atomicAdd(&ssum[col], csum[i]);
        atomicAdd(&ssq[col],  csq[i]);
    }
    __syncthreads();
    // 1024 fp64 atomics per block
#pragma unroll
    for (int t = 0; t < 2; t++) {
        int c = tid + t * 256;
        atomicAdd(&g_colsum[c],   (double)ssum[c]);
        atomicAdd(&g_colsumsq[c], (double)ssq[c]);
    }
}

__global__ void k_bnfinal(const float* __restrict__ bn_gamma,
                          const float* __restrict__ bn_beta,
                          const float* __restrict__ att)
{
    int c = blockIdx.x * blockDim.x + threadIdx.x;
    if (c >= ZDIM) return;
    float mean = (float)(g_colsum[c] * (1.0 / NNODES));
    float var  = (float)(g_colsumsq[c] * (1.0 / NNODES)) - mean * mean;
    float invs = 1.f / sqrtf(var + 1e-5f);
    float a  = att[c];                      // attention >= 0: fold through relu
    float sc = invs * bn_gamma[c];
    g_scale[c] = sc * a;
    g_shift[c] = (bn_beta[c] - mean * sc) * a;
}

// ---------------- LayerNorm (per row of z1 [N,256]) + relu, in place --------
__global__ void k_lnrelu(const float* __restrict__ gam, const float* __restrict__ bet)
{
    int row = blockIdx.x * (blockDim.x >> 5) + (threadIdx.x >> 5);
    if (row >= NNODES) return;
    int lane = threadIdx.x & 31;
    float* p = g_z1 + (size_t)row * MID;
    float v[8];
    float s = 0.f;
#pragma unroll
    for (int i = 0; i < 8; i++) { v[i] = p[lane + 32 * i]; s += v[i]; }
#pragma unroll
    for (int o = 16; o; o >>= 1) s += __shfl_xor_sync(0xffffffffu, s, o);
    float mean = s * (1.f / MID);
    float q = 0.f;
#pragma unroll
    for (int i = 0; i < 8; i++) { float t = v[i] - mean; q += t * t; }
#pragma unroll
    for (int o = 16; o; o >>= 1) q += __shfl_xor_sync(0xffffffffu, q, o);
    float inv = rsqrtf(q * (1.f / MID) + 1e-5f);
#pragma unroll
    for (int i = 0; i < 8; i++) {
        int c = lane + 32 * i;
        p[c] = fmaxf((v[i] - mean) * inv * gam[c] + bet[c], 0.f);
    }
}

// ---------------- launch -----------------------------------------------------
extern "C" void kernel_launch(void* const* d_in, const int* in_sizes, int n_in,
                              void* d_out, int out_size)
{
    const float* x        = (const float*)d_in[0];
    const int*   ei       = (const int*)  d_in[1];
    const float* pos      = (const float*)d_in[2];
    const float* W_ft     = (const float*)d_in[3];
    const float* b_ft     = (const float*)d_in[4];
    const float* W_conv   = (const float*)d_in[5];
    const float* b_conv   = (const float*)d_in[6];
    const float* vf       = (const float*)d_in[7];
    const float* vparams  = (const float*)d_in[8];
    const float* bn_gamma = (const float*)d_in[9];
    const float* bn_beta  = (const float*)d_in[10];
    const float* att      = (const float*)d_in[11];
    const float* W1       = (const float*)d_in[12];
    const float* b1       = (const float*)d_in[13];
    const float* ln_g     = (const float*)d_in[14];
    const float* ln_b     = (const float*)d_in[15];
    const float* W2       = (const float*)d_in[16];
    const float* b2       = (const float*)d_in[17];
    float* out = (float*)d_out;

    float *ph, *phw, *pagg, *pz1;
    cudaGetSymbolAddress((void**)&ph,    g_h);
    cudaGetSymbolAddress((void**)&phw,   g_hw);
    cudaGetSymbolAddress((void**)&pagg,  g_agg);
    cudaGetSymbolAddress((void**)&pz1,   g_z1);

    cudaFuncSetAttribute(k_gemm, cudaFuncAttributeMaxDynamicSharedMemorySize, GSMEM);

    const int ROWB = (NNODES + 127) / 128;  // 391

    // init counters
    k_zero_misc<<<64, 1024>>>();

    // feature transform + conv linear (applied per node; gather commutes)
    k_gemm<<<dim3(1, ROWB), 512, GSMEM>>>(x,  W_ft,   b_ft,   ph,  NNODES, FDIM, HDIM, 1, 0);
    k_gemm<<<dim3(1, ROWB), 512, GSMEM>>>(ph, W_conv, b_conv, phw, NNODES, HDIM, HDIM, 0, 0);

    // edge pass 1: max distance + dst histogram
    k_distmax_hist<<<1024, 256>>>(ei, pos);
    // CSR offsets
    k_scan<<<1, 1024>>>();
    // edge pass 2: per-edge ab factors into CSR slots
    k_reorder<<<(NEDGES + 255) / 256, 256>>>(ei, pos, vf, vparams);
    // gather-aggregate per node + fused BN column stats (block-reduced)
    k_agg<<<512, 256>>>();

    k_bnfinal<<<2, 256>>>(bn_gamma, bn_beta, att);

    // MLP head: relu(BN(agg))*att (fused in GEMM A-path) @ W1^T -> LN+relu -> @ W2^T
    k_gemm<<<dim3(MID / 128, ROWB), 512, GSMEM>>>(pagg, W1, b1, pz1, NNODES, ZDIM, MID, 0, 1);
    k_lnrelu<<<(NNODES + 7) / 8, 256>>>(ln_g, ln_b);
    k_gemm<<<dim3(ODIM / 128, ROWB), 512, GSMEM>>>(pz1, W2, b2, out, NNODES, MID, ODIM, 0, 0);
}

// round 14
// speedup vs baseline: 1.0578x; 1.0578x over previous
#include <cuda_runtime.h>
#include <math.h>
#include <stdint.h>

#define NNODES 50000
#define NEDGES 800000
#define FDIM 128
#define HDIM 128
#define ODIM 128
#define KOBS 4
#define ZDIM 512   /* K*H */
#define MID  256   /* 2*H */

// ---------------- scratch (device globals; no allocation allowed) ----------
__device__ __align__(16) float g_xc [(size_t)NNODES * FDIM];   // tf32-rounded x
__device__ __align__(16) float g_h  [(size_t)NNODES * HDIM];
__device__ __align__(16) float g_hw [(size_t)NNODES * HDIM];
__device__ __align__(16) float g_agg[(size_t)NNODES * ZDIM];
__device__ __align__(16) float g_z1 [(size_t)NNODES * MID];
__device__ __align__(16) float g_wft  [HDIM * FDIM];
__device__ __align__(16) float g_wconv[HDIM * HDIM];
__device__ __align__(16) float g_w1   [MID * ZDIM];
__device__ __align__(16) float g_w2   [ODIM * MID];
__device__ double g_colsum  [ZDIM];
__device__ double g_colsumsq[ZDIM];
__device__ __align__(16) float g_scale[ZDIM];   // bn scale * attention
__device__ __align__(16) float g_shift[ZDIM];   // bn shift * attention
__device__ unsigned int g_distmax_bits;
// CSR structures
__device__ int g_cnt[NNODES];
__device__ int g_off[NNODES + 1];
__device__ int g_cur[NNODES];
__device__ int g_esrc[NEDGES];
__device__ __align__(16) float4 g_eab[NEDGES];

__device__ __forceinline__ float to_tf32(float x) {
    float r;
    asm("cvt.rna.tf32.f32 %0, %1;" : "=f"(r) : "f"(x));
    return r;
}

// ---------------- zero / init ----------------------------------------------
__global__ void k_zero_misc() {
    int i = blockIdx.x * blockDim.x + threadIdx.x;
    if (i == 0) g_distmax_bits = 0u;
    if (i < ZDIM) { g_colsum[i] = 0.0; g_colsumsq[i] = 0.0; }
    for (; i < NNODES; i += gridDim.x * blockDim.x) g_cnt[i] = 0;
}

// ---------------- single-launch tf32 rounding of all GEMM inputs ------------
__global__ void k_round_all(const float* __restrict__ x,
                            const float* __restrict__ wft,
                            const float* __restrict__ wconv,
                            const float* __restrict__ w1,
                            const float* __restrict__ w2)
{
    const int n0 = NNODES * FDIM / 4;
    const int n1 = HDIM * FDIM / 4;
    const int n2 = HDIM * HDIM / 4;
    const int n3 = MID * ZDIM / 4;
    const int n4 = ODIM * MID / 4;
    const int total = n0 + n1 + n2 + n3 + n4;
    int i = blockIdx.x * blockDim.x + threadIdx.x;
    for (; i < total; i += gridDim.x * blockDim.x) {
        const float4* s;
        float4* d;
        int j = i;
        if (j < n0)              { s = (const float4*)x;     d = (float4*)g_xc; }
        else if ((j -= n0) < n1) { s = (const float4*)wft;   d = (float4*)g_wft; }
        else if ((j -= n1) < n2) { s = (const float4*)wconv; d = (float4*)g_wconv; }
        else if ((j -= n2) < n3) { s = (const float4*)w1;    d = (float4*)g_w1; }
        else                     { j -= n3; s = (const float4*)w2; d = (float4*)g_w2; }
        float4 v = s[j];
        v.x = to_tf32(v.x); v.y = to_tf32(v.y);
        v.z = to_tf32(v.z); v.w = to_tf32(v.w);
        d[j] = v;
    }
}

// ---------------- tf32 tensor GEMM, cp.async 2-stage, 2 CTA/SM --------------
// C[r,c] = sum_k A[r,k] * W[c,k] + bias[c]   (A @ W^T + b)
// A and W must be PRE-ROUNDED to tf32 in gmem. 512 threads, tile 128x128,
// BK=32, 16 warps x (32x32).
#define GSM_STAGE 9216          /* floats per stage (A 4608 + W 4608) */
#define GSMEM     73728         /* bytes */

__global__ void __launch_bounds__(512, 2)
k_gemm(const float* __restrict__ A, const float* __restrict__ W,
       const float* __restrict__ bias, float* __restrict__ C,
       int nrows, int kdim, int mcols, int do_relu, int round_out)
{
    extern __shared__ float sm[];
    const int tid  = threadIdx.x;
    const int warp = tid >> 5;
    const int lane = tid & 31;
    const int row0 = blockIdx.y * 128;
    const int col0 = blockIdx.x * 128;
    const int mw = (warp & 3) * 32;
    const int nw = (warp >> 2) * 32;
    const int gq = lane >> 2;
    const int tq = lane & 3;
    const int r_ld = tid >> 3;           // 0..63
    const int kv   = (tid & 7) * 4;      // 0..28

    float acc[2][4][4];
#pragma unroll
    for (int mi = 0; mi < 2; mi++)
#pragma unroll
        for (int ni = 0; ni < 4; ni++)
#pragma unroll
            for (int q = 0; q < 4; q++) acc[mi][ni][q] = 0.f;

#define ISSUE(ST)                                                              \
    do {                                                                       \
        const int k0_ = (ST) * 32;                                             \
        float* dA_ = sm + ((ST) & 1) * GSM_STAGE;                              \
        _Pragma("unroll")                                                      \
        for (int t = 0; t < 2; t++) {                                          \
            int r = r_ld + t * 64;                                             \
            int ar = row0 + r; if (ar > nrows - 1) ar = nrows - 1;             \
            const float* sA = A + (size_t)ar * kdim + k0_ + kv;                \
            uint32_t du = (uint32_t)__cvta_generic_to_shared(dA_ + r * 36 + kv); \
            asm volatile("cp.async.cg.shared.global [%0], [%1], 16;"           \
                         :: "r"(du), "l"(sA));                                 \
            const float* sW = W + (size_t)(col0 + r) * kdim + k0_ + kv;        \
            uint32_t dw = (uint32_t)__cvta_generic_to_shared(dA_ + 4608 + r * 36 + kv); \
            asm volatile("cp.async.cg.shared.global [%0], [%1], 16;"           \
                         :: "r"(dw), "l"(sW));                                 \
        }                                                                      \
        asm volatile("cp.async.commit_group;" ::: "memory");                   \
    } while (0)

    const int nch = kdim >> 5;
    ISSUE(0);
    if (nch > 1) ISSUE(1);

    for (int i = 0; i < nch; i++) {
        if (i < nch - 1) asm volatile("cp.async.wait_group 1;" ::: "memory");
        else             asm volatile("cp.async.wait_group 0;" ::: "memory");
        __syncthreads();
        const float* As = sm + (i & 1) * GSM_STAGE;
        const float* Ws = As + 4608;

#pragma unroll
        for (int j = 0; j < 4; j++) {
            const int kk = j * 8;
            uint32_t af[8], bf[8];
#pragma unroll
            for (int mi = 0; mi < 2; mi++) {
                int r = mw + mi * 16 + gq;
                af[mi * 4 + 0] = __float_as_uint(As[r * 36 + kk + tq]);
                af[mi * 4 + 1] = __float_as_uint(As[(r + 8) * 36 + kk + tq]);
                af[mi * 4 + 2] = __float_as_uint(As[r * 36 + kk + tq + 4]);
                af[mi * 4 + 3] = __float_as_uint(As[(r + 8) * 36 + kk + tq + 4]);
            }
#pragma unroll
            for (int ni = 0; ni < 4; ni++) {
                int cc = nw + ni * 8 + gq;
                bf[ni * 2 + 0] = __float_as_uint(Ws[cc * 36 + kk + tq]);
                bf[ni * 2 + 1] = __float_as_uint(Ws[cc * 36 + kk + tq + 4]);
            }
#pragma unroll
            for (int mi = 0; mi < 2; mi++)
#pragma unroll
                for (int ni = 0; ni < 4; ni++) {
                    asm volatile(
                        "mma.sync.aligned.m16n8k8.row.col.f32.tf32.tf32.f32 "
                        "{%0,%1,%2,%3}, {%4,%5,%6,%7}, {%8,%9}, {%0,%1,%2,%3};"
                        : "+f"(acc[mi][ni][0]), "+f"(acc[mi][ni][1]),
                          "+f"(acc[mi][ni][2]), "+f"(acc[mi][ni][3])
                        : "r"(af[mi * 4 + 0]), "r"(af[mi * 4 + 1]),
                          "r"(af[mi * 4 + 2]), "r"(af[mi * 4 + 3]),
                          "r"(bf[ni * 2 + 0]), "r"(bf[ni * 2 + 1]));
                }
        }
        __syncthreads();
        if (i + 2 < nch) ISSUE(i + 2);
    }

    // ---- epilogue: bias (+ optional relu, optional tf32 rounding) ----
#pragma unroll
    for (int mi = 0; mi < 2; mi++) {
        int r0 = row0 + mw + mi * 16 + gq;
#pragma unroll
        for (int ni = 0; ni < 4; ni++) {
            int ccol = col0 + nw + ni * 8 + tq * 2;
            float b0 = bias[ccol], b1 = bias[ccol + 1];
            float v0 = acc[mi][ni][0] + b0;
            float v1 = acc[mi][ni][1] + b1;
            float v2 = acc[mi][ni][2] + b0;
            float v3 = acc[mi][ni][3] + b1;
            if (do_relu) {
                v0 = fmaxf(v0, 0.f); v1 = fmaxf(v1, 0.f);
                v2 = fmaxf(v2, 0.f); v3 = fmaxf(v3, 0.f);
            }
            if (round_out) {
                v0 = to_tf32(v0); v1 = to_tf32(v1);
                v2 = to_tf32(v2); v3 = to_tf32(v3);
            }
            if (r0 < nrows)
                *(float2*)&C[(size_t)r0 * mcols + ccol] = make_float2(v0, v1);
            if (r0 + 8 < nrows)
                *(float2*)&C[(size_t)(r0 + 8) * mcols + ccol] = make_float2(v2, v3);
        }
    }
}

// ---------------- pass 1 over edges: max distance + dst histogram -----------
__global__ void k_distmax_hist(const int* __restrict__ ei, const float* __restrict__ pos)
{
    int i = blockIdx.x * blockDim.x + threadIdx.x;
    float m = 0.f;
    for (; i < NEDGES; i += gridDim.x * blockDim.x) {
        int s = ei[i], d = ei[NEDGES + i];
        float ax = pos[3 * s + 0] - pos[3 * d + 0];
        float ay = pos[3 * s + 1] - pos[3 * d + 1];
        float az = pos[3 * s + 2] - pos[3 * d + 2];
        m = fmaxf(m, sqrtf(ax * ax + ay * ay + az * az));
        atomicAdd(&g_cnt[d], 1);
    }
#pragma unroll
    for (int o = 16; o; o >>= 1) m = fmaxf(m, __shfl_xor_sync(0xffffffffu, m, o));
    if ((threadIdx.x & 31) == 0) atomicMax(&g_distmax_bits, __float_as_uint(m));
}

// ---------------- exclusive scan of g_cnt -> g_off, g_cur (one block) -------
__global__ void __launch_bounds__(1024) k_scan()
{
    const int CH = (NNODES + 1023) / 1024;   // 49
    __shared__ int wsum[32];
    int t = threadIdx.x;
    int lane = t & 31, wid = t >> 5;
    int base = t * CH;

    int s = 0;
#pragma unroll 4
    for (int i = 0; i < CH; i++) {
        int idx = base + i;
        if (idx < NNODES) s += g_cnt[idx];
    }
    int incl = s;
#pragma unroll
    for (int o = 1; o < 32; o <<= 1) {
        int v = __shfl_up_sync(0xffffffffu, incl, o);
        if (lane >= o) incl += v;
    }
    if (lane == 31) wsum[wid] = incl;
    __syncthreads();
    if (wid == 0) {
        int w = wsum[lane];
        int wi = w;
#pragma unroll
        for (int o = 1; o < 32; o <<= 1) {
            int v = __shfl_up_sync(0xffffffffu, wi, o);
            if (lane >= o) wi += v;
        }
        wsum[lane] = wi - w;   // exclusive warp offsets
    }
    __syncthreads();
    int excl = wsum[wid] + incl - s;
    int run = excl;
    for (int i = 0; i < CH; i++) {
        int idx = base + i;
        if (idx < NNODES) {
            g_off[idx] = run;
            g_cur[idx] = run;
            run += g_cnt[idx];
        }
    }
    if (t == 1023) g_off[NNODES] = NEDGES;
}

// ---------------- pass 2: compute ab[4] per edge, place into CSR order ------
__global__ void k_reorder(const int* __restrict__ ei, const float* __restrict__ pos,
                          const float* __restrict__ vfp, const float* __restrict__ vparams)
{
    int e = blockIdx.x * blockDim.x + threadIdx.x;
    if (e >= NEDGES) return;
    int s = __ldg(&ei[e]);
    int d = __ldg(&ei[NEDGES + e]);

    float ax = pos[3 * s + 0] - pos[3 * d + 0];
    float ay = pos[3 * s + 1] - pos[3 * d + 1];
    float az = pos[3 * s + 2] - pos[3 * d + 2];
    float dist = sqrtf(ax * ax + ay * ay + az * az);
    float dmax = __uint_as_float(g_distmax_bits);
    float r    = dist / dmax;
    float inv  = 1.f / (dist + 1e-8f);
    float dsum = (ax + ay + az) * inv;
    float vf   = vfp[0];

    float4 ab;
    {
        float v, g2;
        v = vf * fminf(r, vparams[0]); g2 = 1.f - v * v + 1e-8f;
        ab.x = sqrtf(g2) / (1.f + v * dsum);
        v = vf * fminf(r, vparams[1]); g2 = 1.f - v * v + 1e-8f;
        ab.y = sqrtf(g2) / (1.f + v * dsum);
        v = vf * fminf(r, vparams[2]); g2 = 1.f - v * v + 1e-8f;
        ab.z = sqrtf(g2) / (1.f + v * dsum);
        v = vf * fminf(r, vparams[3]); g2 = 1.f - v * v + 1e-8f;
        ab.w = sqrtf(g2) / (1.f + v * dsum);
    }
    int p = atomicAdd(&g_cur[d], 1);
    g_esrc[p] = s;
    g_eab[p]  = ab;
}

// ---------------- aggregate: one warp per node + fused BN column stats ------
// Stats: per-thread float partials -> block smem reduction -> 1024 fp64
// atomics per block (512 blocks => ~512 serialized ops/address, ~9us).
#define ACCUM(AB, HV)                                                        \
    do {                                                                     \
        acc[ 0] = fmaf(AB.x, HV.x, acc[ 0]); acc[ 1] = fmaf(AB.x, HV.y, acc[ 1]); \
        acc[ 2] = fmaf(AB.x, HV.z, acc[ 2]); acc[ 3] = fmaf(AB.x, HV.w, acc[ 3]); \
        acc[ 4] = fmaf(AB.y, HV.x, acc[ 4]); acc[ 5] = fmaf(AB.y, HV.y, acc[ 5]); \
        acc[ 6] = fmaf(AB.y, HV.z, acc[ 6]); acc[ 7] = fmaf(AB.y, HV.w, acc[ 7]); \
        acc[ 8] = fmaf(AB.z, HV.x, acc[ 8]); acc[ 9] = fmaf(AB.z, HV.y, acc[ 9]); \
        acc[10] = fmaf(AB.z, HV.z, acc[10]); acc[11] = fmaf(AB.z, HV.w, acc[11]); \
        acc[12] = fmaf(AB.w, HV.x, acc[12]); acc[13] = fmaf(AB.w, HV.y, acc[13]); \
        acc[14] = fmaf(AB.w, HV.z, acc[14]); acc[15] = fmaf(AB.w, HV.w, acc[15]); \
    } while (0)

__global__ void __launch_bounds__(256)
k_agg()
{
    __shared__ float ssum[ZDIM], ssq[ZDIM];
    const int tid  = threadIdx.x;
    const int lane = tid & 31;
    const int wid  = (blockIdx.x << 3) + (tid >> 5);
    const int nwarps = gridDim.x << 3;
    const float* __restrict__ hw = g_hw;
    const int*   __restrict__ esrc = g_esrc;
    const float4* __restrict__ eab = g_eab;

    ssum[tid] = 0.f; ssum[tid + 256] = 0.f;
    ssq[tid]  = 0.f; ssq[tid + 256]  = 0.f;
    __syncthreads();

    float csum[16], csq[16];
#pragma unroll
    for (int i = 0; i < 16; i++) { csum[i] = 0.f; csq[i] = 0.f; }

    for (int node = wid; node < NNODES; node += nwarps) {
        float acc[16];
#pragma unroll
        for (int i = 0; i < 16; i++) acc[i] = 0.f;
        const int p0 = g_off[node], p1 = g_off[node + 1];
        int p = p0;
        for (; p + 4 <= p1; p += 4) {
            int s0 = esrc[p + 0], s1 = esrc[p + 1];
            int s2 = esrc[p + 2], s3 = esrc[p + 3];
            float4 ab0 = eab[p + 0], ab1 = eab[p + 1];
            float4 ab2 = eab[p + 2], ab3 = eab[p + 3];
            float4 h0 = *(const float4*)&hw[(size_t)s0 * HDIM + lane * 4];
            float4 h1 = *(const float4*)&hw[(size_t)s1 * HDIM + lane * 4];
            float4 h2 = *(const float4*)&hw[(size_t)s2 * HDIM + lane * 4];
            float4 h3 = *(const float4*)&hw[(size_t)s3 * HDIM + lane * 4];
            ACCUM(ab0, h0);
            ACCUM(ab1, h1);
            ACCUM(ab2, h2);
            ACCUM(ab3, h3);
        }
        for (; p < p1; p++) {
            int s = esrc[p];
            float4 ab = eab[p];
            float4 h = *(const float4*)&hw[(size_t)s * HDIM + lane * 4];
            ACCUM(ab, h);
        }
        float* op = &g_agg[(size_t)node * ZDIM + lane * 4];
        *(float4*)(op + 0 * HDIM) = make_float4(acc[ 0], acc[ 1], acc[ 2], acc[ 3]);
        *(float4*)(op + 1 * HDIM) = make_float4(acc[ 4], acc[ 5], acc[ 6], acc[ 7]);
        *(float4*)(op + 2 * HDIM) = make_float4(acc[ 8], acc[ 9], acc[10], acc[11]);
        *(float4*)(op + 3 * HDIM) = make_float4(acc[12], acc[13], acc[14], acc[15]);
#pragma unroll
        for (int i = 0; i < 16; i++) {
            csum[i] += acc[i];
            csq[i]   = fmaf(acc[i], acc[i], csq[i]);
        }
    }

    // block-level reduction into smem (float atomics)
#pragma unroll
    for (int i = 0; i < 16; i++) {
        int col = (i >> 2) * HDIM + lane * 4 + (i & 3);
        atomicAdd(&ssum[col], csum[i]);
        atomicAdd(&ssq[col],  csq[i]);
    }
    __syncthreads();
    // 1024 fp64 atomics per block
#pragma unroll
    for (int t = 0; t < 2; t++) {
        int c = tid + t * 256;
        atomicAdd(&g_colsum[c],   (double)ssum[c]);
        atomicAdd(&g_colsumsq[c], (double)ssq[c]);
    }
}

__global__ void k_bnfinal(const float* __restrict__ bn_gamma,
                          const float* __restrict__ bn_beta,
                          const float* __restrict__ att)
{
    int c = blockIdx.x * blockDim.x + threadIdx.x;
    if (c >= ZDIM) return;
    float mean = (float)(g_colsum[c] * (1.0 / NNODES));
    float var  = (float)(g_colsumsq[c] * (1.0 / NNODES)) - mean * mean;
    float invs = 1.f / sqrtf(var + 1e-5f);
    float a  = att[c];                      // attention >= 0: fold through relu
    float sc = invs * bn_gamma[c];
    g_scale[c] = sc * a;
    g_shift[c] = (bn_beta[c] - mean * sc) * a;
}

// ---------------- BN + relu + attention + tf32 round (in place on agg) ------
__global__ void k_bnact()
{
    size_t i = (size_t)blockIdx.x * blockDim.x + threadIdx.x;
    size_t total = (size_t)NNODES * ZDIM / 4;
    for (; i < total; i += (size_t)gridDim.x * blockDim.x) {
        int c = (int)((i * 4) & (ZDIM - 1));
        float4 v = ((float4*)g_agg)[i];
        v.x = to_tf32(fmaxf(fmaf(v.x, g_scale[c + 0], g_shift[c + 0]), 0.f));
        v.y = to_tf32(fmaxf(fmaf(v.y, g_scale[c + 1], g_shift[c + 1]), 0.f));
        v.z = to_tf32(fmaxf(fmaf(v.z, g_scale[c + 2], g_shift[c + 2]), 0.f));
        v.w = to_tf32(fmaxf(fmaf(v.w, g_scale[c + 3], g_shift[c + 3]), 0.f));
        ((float4*)g_agg)[i] = v;
    }
}

// ---------------- LayerNorm (per row of z1 [N,256]) + relu + round ----------
__global__ void k_lnrelu(const float* __restrict__ gam, const float* __restrict__ bet)
{
    int row = blockIdx.x * (blockDim.x >> 5) + (threadIdx.x >> 5);
    if (row >= NNODES) return;
    int lane = threadIdx.x & 31;
    float* p = g_z1 + (size_t)row * MID;
    float v[8];
    float s = 0.f;
#pragma unroll
    for (int i = 0; i < 8; i++) { v[i] = p[lane + 32 * i]; s += v[i]; }
#pragma unroll
    for (int o = 16; o; o >>= 1) s += __shfl_xor_sync(0xffffffffu, s, o);
    float mean = s * (1.f / MID);
    float q = 0.f;
#pragma unroll
    for (int i = 0; i < 8; i++) { float t = v[i] - mean; q += t * t; }
#pragma unroll
    for (int o = 16; o; o >>= 1) q += __shfl_xor_sync(0xffffffffu, q, o);
    float inv = rsqrtf(q * (1.f / MID) + 1e-5f);
#pragma unroll
    for (int i = 0; i < 8; i++) {
        int c = lane + 32 * i;
        p[c] = to_tf32(fmaxf((v[i] - mean) * inv * gam[c] + bet[c], 0.f));
    }
}

// ---------------- launch -----------------------------------------------------
extern "C" void kernel_launch(void* const* d_in, const int* in_sizes, int n_in,
                              void* d_out, int out_size)
{
    const float* x        = (const float*)d_in[0];
    const int*   ei       = (const int*)  d_in[1];
    const float* pos      = (const float*)d_in[2];
    const float* W_ft     = (const float*)d_in[3];
    const float* b_ft     = (const float*)d_in[4];
    const float* W_conv   = (const float*)d_in[5];
    const float* b_conv   = (const float*)d_in[6];
    const float* vf       = (const float*)d_in[7];
    const float* vparams  = (const float*)d_in[8];
    const float* bn_gamma = (const float*)d_in[9];
    const float* bn_beta  = (const float*)d_in[10];
    const float* att      = (const float*)d_in[11];
    const float* W1       = (const float*)d_in[12];
    const float* b1       = (const float*)d_in[13];
    const float* ln_g     = (const float*)d_in[14];
    const float* ln_b     = (const float*)d_in[15];
    const float* W2       = (const float*)d_in[16];
    const float* b2       = (const float*)d_in[17];
    float* out = (float*)d_out;

    float *pxc, *ph, *phw, *pagg, *pz1, *pwft, *pwconv, *pw1, *pw2;
    cudaGetSymbolAddress((void**)&pxc,   g_xc);
    cudaGetSymbolAddress((void**)&ph,    g_h);
    cudaGetSymbolAddress((void**)&phw,   g_hw);
    cudaGetSymbolAddress((void**)&pagg,  g_agg);
    cudaGetSymbolAddress((void**)&pz1,   g_z1);
    cudaGetSymbolAddress((void**)&pwft,  g_wft);
    cudaGetSymbolAddress((void**)&pwconv,g_wconv);
    cudaGetSymbolAddress((void**)&pw1,   g_w1);
    cudaGetSymbolAddress((void**)&pw2,   g_w2);

    cudaFuncSetAttribute(k_gemm, cudaFuncAttributeMaxDynamicSharedMemorySize, GSMEM);

    const int ROWB = (NNODES + 127) / 128;  // 391

    // init counters
    k_zero_misc<<<64, 1024>>>();

    // tf32-round ALL GEMM inputs in one launch
    k_round_all<<<1024, 256>>>(x, W_ft, W_conv, W1, W2);

    // feature transform + conv linear (applied per node; gather commutes)
    k_gemm<<<dim3(1, ROWB), 512, GSMEM>>>(pxc, pwft,   b_ft,   ph,  NNODES, FDIM, HDIM, 1, 1);
    k_gemm<<<dim3(1, ROWB), 512, GSMEM>>>(ph,  pwconv, b_conv, phw, NNODES, HDIM, HDIM, 0, 0);

    // edge pass 1: max distance + dst histogram
    k_distmax_hist<<<1024, 256>>>(ei, pos);
    // CSR offsets
    k_scan<<<1, 1024>>>();
    // edge pass 2: per-edge ab factors into CSR slots
    k_reorder<<<(NEDGES + 255) / 256, 256>>>(ei, pos, vf, vparams);
    // gather-aggregate per node + fused BN column stats (block-reduced)
    k_agg<<<512, 256>>>();

    // BatchNorm: scale/shift -> apply (+relu+att+tf32 round)
    k_bnfinal<<<2, 256>>>(bn_gamma, bn_beta, att);
    k_bnact<<<8192, 256>>>();

    // MLP head: agg' @ W1^T -> LN+relu -> @ W2^T
    k_gemm<<<dim3(MID / 128, ROWB), 512, GSMEM>>>(pagg, pw1, b1, pz1, NNODES, ZDIM, MID, 0, 0);
    k_lnrelu<<<(NNODES + 7) / 8, 256>>>(ln_g, ln_b);
    k_gemm<<<dim3(ODIM / 128, ROWB), 512, GSMEM>>>(pz1, pw2, b2, out, NNODES, MID, ODIM, 0, 0);
}

// round 15
// speedup vs baseline: 1.0932x; 1.0335x over previous
#include <cuda_runtime.h>
#include <math.h>
#include <stdint.h>

#define NNODES 50000
#define NEDGES 800000
#define FDIM 128
#define HDIM 128
#define ODIM 128
#define KOBS 4
#define ZDIM 512   /* K*H */
#define MID  256   /* 2*H */

// ---------------- scratch (device globals; no allocation allowed) ----------
__device__ __align__(16) float g_xc [(size_t)NNODES * FDIM];   // tf32-rounded x
__device__ __align__(16) float g_h  [(size_t)NNODES * HDIM];
__device__ __align__(16) float g_hw [(size_t)NNODES * HDIM];
__device__ __align__(16) float g_agg[(size_t)NNODES * ZDIM];
__device__ __align__(16) float g_z1 [(size_t)NNODES * MID];
__device__ __align__(16) float g_wft  [HDIM * FDIM];
__device__ __align__(16) float g_wconv[HDIM * HDIM];
__device__ __align__(16) float g_w1   [MID * ZDIM];
__device__ __align__(16) float g_w2   [ODIM * MID];
__device__ double g_colsum  [ZDIM];
__device__ double g_colsumsq[ZDIM];
__device__ __align__(16) float g_scale[ZDIM];   // bn scale * attention
__device__ __align__(16) float g_shift[ZDIM];   // bn shift * attention
__device__ unsigned int g_distmax_bits;
// CSR structures
__device__ int g_cnt[NNODES];
__device__ int g_off[NNODES + 1];
__device__ int g_cur[NNODES];
__device__ int g_esrc[NEDGES];
__device__ __align__(16) float4 g_eab[NEDGES];

__device__ __forceinline__ float to_tf32(float x) {
    float r;
    asm("cvt.rna.tf32.f32 %0, %1;" : "=f"(r) : "f"(x));
    return r;
}

// ---------------- zero / init ----------------------------------------------
__global__ void k_zero_misc() {
    int i = blockIdx.x * blockDim.x + threadIdx.x;
    if (i == 0) g_distmax_bits = 0u;
    if (i < ZDIM) { g_colsum[i] = 0.0; g_colsumsq[i] = 0.0; }
    for (; i < NNODES; i += gridDim.x * blockDim.x) g_cnt[i] = 0;
}

// ---------------- single-launch tf32 rounding of all GEMM inputs ------------
__global__ void k_round_all(const float* __restrict__ x,
                            const float* __restrict__ wft,
                            const float* __restrict__ wconv,
                            const float* __restrict__ w1,
                            const float* __restrict__ w2)
{
    const int n0 = NNODES * FDIM / 4;
    const int n1 = HDIM * FDIM / 4;
    const int n2 = HDIM * HDIM / 4;
    const int n3 = MID * ZDIM / 4;
    const int n4 = ODIM * MID / 4;
    const int total = n0 + n1 + n2 + n3 + n4;
    int i = blockIdx.x * blockDim.x + threadIdx.x;
    for (; i < total; i += gridDim.x * blockDim.x) {
        const float4* s;
        float4* d;
        int j = i;
        if (j < n0)              { s = (const float4*)x;     d = (float4*)g_xc; }
        else if ((j -= n0) < n1) { s = (const float4*)wft;   d = (float4*)g_wft; }
        else if ((j -= n1) < n2) { s = (const float4*)wconv; d = (float4*)g_wconv; }
        else if ((j -= n2) < n3) { s = (const float4*)w1;    d = (float4*)g_w1; }
        else                     { j -= n3; s = (const float4*)w2; d = (float4*)g_w2; }
        float4 v = s[j];
        v.x = to_tf32(v.x); v.y = to_tf32(v.y);
        v.z = to_tf32(v.z); v.w = to_tf32(v.w);
        d[j] = v;
    }
}

// ---------------- tf32 tensor GEMM, cp.async 2-stage, 2 CTA/SM --------------
// C[r,c] = sum_k A[r,k] * W[c,k] + bias[c]   (A @ W^T + b)
// A and W must be PRE-ROUNDED to tf32 in gmem. 512 threads, tile 128x128,
// BK=32, 16 warps x (32x32).
#define GSM_STAGE 9216          /* floats per stage (A 4608 + W 4608) */
#define GSMEM     73728         /* bytes */

__global__ void __launch_bounds__(512, 2)
k_gemm(const float* __restrict__ A, const float* __restrict__ W,
       const float* __restrict__ bias, float* __restrict__ C,
       int nrows, int kdim, int mcols, int do_relu, int round_out)
{
    extern __shared__ float sm[];
    const int tid  = threadIdx.x;
    const int warp = tid >> 5;
    const int lane = tid & 31;
    const int row0 = blockIdx.y * 128;
    const int col0 = blockIdx.x * 128;
    const int mw = (warp & 3) * 32;
    const int nw = (warp >> 2) * 32;
    const int gq = lane >> 2;
    const int tq = lane & 3;
    const int r_ld = tid >> 3;           // 0..63
    const int kv   = (tid & 7) * 4;      // 0..28

    float acc[2][4][4];
#pragma unroll
    for (int mi = 0; mi < 2; mi++)
#pragma unroll
        for (int ni = 0; ni < 4; ni++)
#pragma unroll
            for (int q = 0; q < 4; q++) acc[mi][ni][q] = 0.f;

#define ISSUE(ST)                                                              \
    do {                                                                       \
        const int k0_ = (ST) * 32;                                             \
        float* dA_ = sm + ((ST) & 1) * GSM_STAGE;                              \
        _Pragma("unroll")                                                      \
        for (int t = 0; t < 2; t++) {                                          \
            int r = r_ld + t * 64;                                             \
            int ar = row0 + r; if (ar > nrows - 1) ar = nrows - 1;             \
            const float* sA = A + (size_t)ar * kdim + k0_ + kv;                \
            uint32_t du = (uint32_t)__cvta_generic_to_shared(dA_ + r * 36 + kv); \
            asm volatile("cp.async.cg.shared.global [%0], [%1], 16;"           \
                         :: "r"(du), "l"(sA));                                 \
            const float* sW = W + (size_t)(col0 + r) * kdim + k0_ + kv;        \
            uint32_t dw = (uint32_t)__cvta_generic_to_shared(dA_ + 4608 + r * 36 + kv); \
            asm volatile("cp.async.cg.shared.global [%0], [%1], 16;"           \
                         :: "r"(dw), "l"(sW));                                 \
        }                                                                      \
        asm volatile("cp.async.commit_group;" ::: "memory");                   \
    } while (0)

    const int nch = kdim >> 5;
    ISSUE(0);
    if (nch > 1) ISSUE(1);

    for (int i = 0; i < nch; i++) {
        if (i < nch - 1) asm volatile("cp.async.wait_group 1;" ::: "memory");
        else             asm volatile("cp.async.wait_group 0;" ::: "memory");
        __syncthreads();
        const float* As = sm + (i & 1) * GSM_STAGE;
        const float* Ws = As + 4608;

#pragma unroll
        for (int j = 0; j < 4; j++) {
            const int kk = j * 8;
            uint32_t af[8], bf[8];
#pragma unroll
            for (int mi = 0; mi < 2; mi++) {
                int r = mw + mi * 16 + gq;
                af[mi * 4 + 0] = __float_as_uint(As[r * 36 + kk + tq]);
                af[mi * 4 + 1] = __float_as_uint(As[(r + 8) * 36 + kk + tq]);
                af[mi * 4 + 2] = __float_as_uint(As[r * 36 + kk + tq + 4]);
                af[mi * 4 + 3] = __float_as_uint(As[(r + 8) * 36 + kk + tq + 4]);
            }
#pragma unroll
            for (int ni = 0; ni < 4; ni++) {
                int cc = nw + ni * 8 + gq;
                bf[ni * 2 + 0] = __float_as_uint(Ws[cc * 36 + kk + tq]);
                bf[ni * 2 + 1] = __float_as_uint(Ws[cc * 36 + kk + tq + 4]);
            }
#pragma unroll
            for (int mi = 0; mi < 2; mi++)
#pragma unroll
                for (int ni = 0; ni < 4; ni++) {
                    asm volatile(
                        "mma.sync.aligned.m16n8k8.row.col.f32.tf32.tf32.f32 "
                        "{%0,%1,%2,%3}, {%4,%5,%6,%7}, {%8,%9}, {%0,%1,%2,%3};"
                        : "+f"(acc[mi][ni][0]), "+f"(acc[mi][ni][1]),
                          "+f"(acc[mi][ni][2]), "+f"(acc[mi][ni][3])
                        : "r"(af[mi * 4 + 0]), "r"(af[mi * 4 + 1]),
                          "r"(af[mi * 4 + 2]), "r"(af[mi * 4 + 3]),
                          "r"(bf[ni * 2 + 0]), "r"(bf[ni * 2 + 1]));
                }
        }
        __syncthreads();
        if (i + 2 < nch) ISSUE(i + 2);
    }

    // ---- epilogue: bias (+ optional relu, optional tf32 rounding) ----
#pragma unroll
    for (int mi = 0; mi < 2; mi++) {
        int r0 = row0 + mw + mi * 16 + gq;
#pragma unroll
        for (int ni = 0; ni < 4; ni++) {
            int ccol = col0 + nw + ni * 8 + tq * 2;
            float b0 = bias[ccol], b1 = bias[ccol + 1];
            float v0 = acc[mi][ni][0] + b0;
            float v1 = acc[mi][ni][1] + b1;
            float v2 = acc[mi][ni][2] + b0;
            float v3 = acc[mi][ni][3] + b1;
            if (do_relu) {
                v0 = fmaxf(v0, 0.f); v1 = fmaxf(v1, 0.f);
                v2 = fmaxf(v2, 0.f); v3 = fmaxf(v3, 0.f);
            }
            if (round_out) {
                v0 = to_tf32(v0); v1 = to_tf32(v1);
                v2 = to_tf32(v2); v3 = to_tf32(v3);
            }
            if (r0 < nrows)
                *(float2*)&C[(size_t)r0 * mcols + ccol] = make_float2(v0, v1);
            if (r0 + 8 < nrows)
                *(float2*)&C[(size_t)(r0 + 8) * mcols + ccol] = make_float2(v2, v3);
        }
    }
}

// ---------------- pass 1 over edges: max distance + dst histogram -----------
__global__ void k_distmax_hist(const int* __restrict__ ei, const float* __restrict__ pos)
{
    int i = blockIdx.x * blockDim.x + threadIdx.x;
    float m = 0.f;
    for (; i < NEDGES; i += gridDim.x * blockDim.x) {
        int s = ei[i], d = ei[NEDGES + i];
        float ax = pos[3 * s + 0] - pos[3 * d + 0];
        float ay = pos[3 * s + 1] - pos[3 * d + 1];
        float az = pos[3 * s + 2] - pos[3 * d + 2];
        m = fmaxf(m, sqrtf(ax * ax + ay * ay + az * az));
        atomicAdd(&g_cnt[d], 1);
    }
#pragma unroll
    for (int o = 16; o; o >>= 1) m = fmaxf(m, __shfl_xor_sync(0xffffffffu, m, o));
    if ((threadIdx.x & 31) == 0) atomicMax(&g_distmax_bits, __float_as_uint(m));
}

// ---------------- exclusive scan of g_cnt -> g_off, g_cur (one block) -------
__global__ void __launch_bounds__(1024) k_scan()
{
    const int CH = (NNODES + 1023) / 1024;   // 49
    __shared__ int wsum[32];
    int t = threadIdx.x;
    int lane = t & 31, wid = t >> 5;
    int base = t * CH;

    int s = 0;
#pragma unroll 4
    for (int i = 0; i < CH; i++) {
        int idx = base + i;
        if (idx < NNODES) s += g_cnt[idx];
    }
    int incl = s;
#pragma unroll
    for (int o = 1; o < 32; o <<= 1) {
        int v = __shfl_up_sync(0xffffffffu, incl, o);
        if (lane >= o) incl += v;
    }
    if (lane == 31) wsum[wid] = incl;
    __syncthreads();
    if (wid == 0) {
        int w = wsum[lane];
        int wi = w;
#pragma unroll
        for (int o = 1; o < 32; o <<= 1) {
            int v = __shfl_up_sync(0xffffffffu, wi, o);
            if (lane >= o) wi += v;
        }
        wsum[lane] = wi - w;   // exclusive warp offsets
    }
    __syncthreads();
    int excl = wsum[wid] + incl - s;
    int run = excl;
    for (int i = 0; i < CH; i++) {
        int idx = base + i;
        if (idx < NNODES) {
            g_off[idx] = run;
            g_cur[idx] = run;
            run += g_cnt[idx];
        }
    }
    if (t == 1023) g_off[NNODES] = NEDGES;
}

// ---------------- pass 2: compute ab[4] per edge, place into CSR order ------
__global__ void k_reorder(const int* __restrict__ ei, const float* __restrict__ pos,
                          const float* __restrict__ vfp, const float* __restrict__ vparams)
{
    int e = blockIdx.x * blockDim.x + threadIdx.x;
    if (e >= NEDGES) return;
    int s = __ldg(&ei[e]);
    int d = __ldg(&ei[NEDGES + e]);

    float ax = pos[3 * s + 0] - pos[3 * d + 0];
    float ay = pos[3 * s + 1] - pos[3 * d + 1];
    float az = pos[3 * s + 2] - pos[3 * d + 2];
    float dist = sqrtf(ax * ax + ay * ay + az * az);
    float dmax = __uint_as_float(g_distmax_bits);
    float r    = dist / dmax;
    float inv  = 1.f / (dist + 1e-8f);
    float dsum = (ax + ay + az) * inv;
    float vf   = vfp[0];

    float4 ab;
    {
        float v, g2;
        v = vf * fminf(r, vparams[0]); g2 = 1.f - v * v + 1e-8f;
        ab.x = sqrtf(g2) / (1.f + v * dsum);
        v = vf * fminf(r, vparams[1]); g2 = 1.f - v * v + 1e-8f;
        ab.y = sqrtf(g2) / (1.f + v * dsum);
        v = vf * fminf(r, vparams[2]); g2 = 1.f - v * v + 1e-8f;
        ab.z = sqrtf(g2) / (1.f + v * dsum);
        v = vf * fminf(r, vparams[3]); g2 = 1.f - v * v + 1e-8f;
        ab.w = sqrtf(g2) / (1.f + v * dsum);
    }
    int p = atomicAdd(&g_cur[d], 1);
    g_esrc[p] = s;
    g_eab[p]  = ab;
}

// ---------------- aggregate: one warp per node (no stats fusion) -------------
#define ACCUM(AB, HV)                                                        \
    do {                                                                     \
        acc[ 0] = fmaf(AB.x, HV.x, acc[ 0]); acc[ 1] = fmaf(AB.x, HV.y, acc[ 1]); \
        acc[ 2] = fmaf(AB.x, HV.z, acc[ 2]); acc[ 3] = fmaf(AB.x, HV.w, acc[ 3]); \
        acc[ 4] = fmaf(AB.y, HV.x, acc[ 4]); acc[ 5] = fmaf(AB.y, HV.y, acc[ 5]); \
        acc[ 6] = fmaf(AB.y, HV.z, acc[ 6]); acc[ 7] = fmaf(AB.y, HV.w, acc[ 7]); \
        acc[ 8] = fmaf(AB.z, HV.x, acc[ 8]); acc[ 9] = fmaf(AB.z, HV.y, acc[ 9]); \
        acc[10] = fmaf(AB.z, HV.z, acc[10]); acc[11] = fmaf(AB.z, HV.w, acc[11]); \
        acc[12] = fmaf(AB.w, HV.x, acc[12]); acc[13] = fmaf(AB.w, HV.y, acc[13]); \
        acc[14] = fmaf(AB.w, HV.z, acc[14]); acc[15] = fmaf(AB.w, HV.w, acc[15]); \
    } while (0)

__global__ void __launch_bounds__(256)
k_agg()
{
    const int lane = threadIdx.x & 31;
    const int wid  = (blockIdx.x << 3) + (threadIdx.x >> 5);
    const int nwarps = gridDim.x << 3;
    const float* __restrict__ hw = g_hw;
    const int*   __restrict__ esrc = g_esrc;
    const float4* __restrict__ eab = g_eab;

    for (int node = wid; node < NNODES; node += nwarps) {
        float acc[16];
#pragma unroll
        for (int i = 0; i < 16; i++) acc[i] = 0.f;
        const int p0 = g_off[node], p1 = g_off[node + 1];
        int p = p0;
        for (; p + 4 <= p1; p += 4) {
            int s0 = esrc[p + 0], s1 = esrc[p + 1];
            int s2 = esrc[p + 2], s3 = esrc[p + 3];
            float4 ab0 = eab[p + 0], ab1 = eab[p + 1];
            float4 ab2 = eab[p + 2], ab3 = eab[p + 3];
            float4 h0 = *(const float4*)&hw[(size_t)s0 * HDIM + lane * 4];
            float4 h1 = *(const float4*)&hw[(size_t)s1 * HDIM + lane * 4];
            float4 h2 = *(const float4*)&hw[(size_t)s2 * HDIM + lane * 4];
            float4 h3 = *(const float4*)&hw[(size_t)s3 * HDIM + lane * 4];
            ACCUM(ab0, h0);
            ACCUM(ab1, h1);
            ACCUM(ab2, h2);
            ACCUM(ab3, h3);
        }
        for (; p < p1; p++) {
            int s = esrc[p];
            float4 ab = eab[p];
            float4 h = *(const float4*)&hw[(size_t)s * HDIM + lane * 4];
            ACCUM(ab, h);
        }
        float* op = &g_agg[(size_t)node * ZDIM + lane * 4];
        *(float4*)(op + 0 * HDIM) = make_float4(acc[ 0], acc[ 1], acc[ 2], acc[ 3]);
        *(float4*)(op + 1 * HDIM) = make_float4(acc[ 4], acc[ 5], acc[ 6], acc[ 7]);
        *(float4*)(op + 2 * HDIM) = make_float4(acc[ 8], acc[ 9], acc[10], acc[11]);
        *(float4*)(op + 3 * HDIM) = make_float4(acc[12], acc[13], acc[14], acc[15]);
    }
}

// ---------------- BN column stats, coalesced (thread = column) --------------
__global__ void __launch_bounds__(512) k_colstats()
{
    const int c  = threadIdx.x;              // column 0..511
    const int r0 = blockIdx.x * 200;         // grid.x = 250
    int r1 = r0 + 200; if (r1 > NNODES) r1 = NNODES;
    float s = 0.f, s2 = 0.f;
    const float* p = g_agg + (size_t)r0 * ZDIM + c;
#pragma unroll 4
    for (int r = r0; r < r1; r++, p += ZDIM) {
        float v = *p;
        s += v; s2 = fmaf(v, v, s2);
    }
    atomicAdd(&g_colsum[c],   (double)s);
    atomicAdd(&g_colsumsq[c], (double)s2);
}

__global__ void k_bnfinal(const float* __restrict__ bn_gamma,
                          const float* __restrict__ bn_beta,
                          const float* __restrict__ att)
{
    int c = blockIdx.x * blockDim.x + threadIdx.x;
    if (c >= ZDIM) return;
    float mean = (float)(g_colsum[c] * (1.0 / NNODES));
    float var  = (float)(g_colsumsq[c] * (1.0 / NNODES)) - mean * mean;
    float invs = 1.f / sqrtf(var + 1e-5f);
    float a  = att[c];                      // attention >= 0: fold through relu
    float sc = invs * bn_gamma[c];
    g_scale[c] = sc * a;
    g_shift[c] = (bn_beta[c] - mean * sc) * a;
}

// ---------------- BN + relu + attention + tf32 round (in place on agg) ------
__global__ void k_bnact()
{
    size_t i = (size_t)blockIdx.x * blockDim.x + threadIdx.x;
    size_t total = (size_t)NNODES * ZDIM / 4;
    for (; i < total; i += (size_t)gridDim.x * blockDim.x) {
        int c = (int)((i * 4) & (ZDIM - 1));
        float4 v = ((float4*)g_agg)[i];
        v.x = to_tf32(fmaxf(fmaf(v.x, g_scale[c + 0], g_shift[c + 0]), 0.f));
        v.y = to_tf32(fmaxf(fmaf(v.y, g_scale[c + 1], g_shift[c + 1]), 0.f));
        v.z = to_tf32(fmaxf(fmaf(v.z, g_scale[c + 2], g_shift[c + 2]), 0.f));
        v.w = to_tf32(fmaxf(fmaf(v.w, g_scale[c + 3], g_shift[c + 3]), 0.f));
        ((float4*)g_agg)[i] = v;
    }
}

// ---------------- LayerNorm (per row of z1 [N,256]) + relu + round ----------
__global__ void k_lnrelu(const float* __restrict__ gam, const float* __restrict__ bet)
{
    int row = blockIdx.x * (blockDim.x >> 5) + (threadIdx.x >> 5);
    if (row >= NNODES) return;
    int lane = threadIdx.x & 31;
    float* p = g_z1 + (size_t)row * MID;
    float v[8];
    float s = 0.f;
#pragma unroll
    for (int i = 0; i < 8; i++) { v[i] = p[lane + 32 * i]; s += v[i]; }
#pragma unroll
    for (int o = 16; o; o >>= 1) s += __shfl_xor_sync(0xffffffffu, s, o);
    float mean = s * (1.f / MID);
    float q = 0.f;
#pragma unroll
    for (int i = 0; i < 8; i++) { float t = v[i] - mean; q += t * t; }
#pragma unroll
    for (int o = 16; o; o >>= 1) q += __shfl_xor_sync(0xffffffffu, q, o);
    float inv = rsqrtf(q * (1.f / MID) + 1e-5f);
#pragma unroll
    for (int i = 0; i < 8; i++) {
        int c = lane + 32 * i;
        p[c] = to_tf32(fmaxf((v[i] - mean) * inv * gam[c] + bet[c], 0.f));
    }
}

// ---------------- launch -----------------------------------------------------
extern "C" void kernel_launch(void* const* d_in, const int* in_sizes, int n_in,
                              void* d_out, int out_size)
{
    const float* x        = (const float*)d_in[0];
    const int*   ei       = (const int*)  d_in[1];
    const float* pos      = (const float*)d_in[2];
    const float* W_ft     = (const float*)d_in[3];
    const float* b_ft     = (const float*)d_in[4];
    const float* W_conv   = (const float*)d_in[5];
    const float* b_conv   = (const float*)d_in[6];
    const float* vf       = (const float*)d_in[7];
    const float* vparams  = (const float*)d_in[8];
    const float* bn_gamma = (const float*)d_in[9];
    const float* bn_beta  = (const float*)d_in[10];
    const float* att      = (const float*)d_in[11];
    const float* W1       = (const float*)d_in[12];
    const float* b1       = (const float*)d_in[13];
    const float* ln_g     = (const float*)d_in[14];
    const float* ln_b     = (const float*)d_in[15];
    const float* W2       = (const float*)d_in[16];
    const float* b2       = (const float*)d_in[17];
    float* out = (float*)d_out;

    float *pxc, *ph, *phw, *pagg, *pz1, *pwft, *pwconv, *pw1, *pw2;
    cudaGetSymbolAddress((void**)&pxc,   g_xc);
    cudaGetSymbolAddress((void**)&ph,    g_h);
    cudaGetSymbolAddress((void**)&phw,   g_hw);
    cudaGetSymbolAddress((void**)&pagg,  g_agg);
    cudaGetSymbolAddress((void**)&pz1,   g_z1);
    cudaGetSymbolAddress((void**)&pwft,  g_wft);
    cudaGetSymbolAddress((void**)&pwconv,g_wconv);
    cudaGetSymbolAddress((void**)&pw1,   g_w1);
    cudaGetSymbolAddress((void**)&pw2,   g_w2);

    cudaFuncSetAttribute(k_gemm, cudaFuncAttributeMaxDynamicSharedMemorySize, GSMEM);

    const int ROWB = (NNODES + 127) / 128;  // 391

    // init counters
    k_zero_misc<<<64, 1024>>>();

    // tf32-round ALL GEMM inputs in one launch
    k_round_all<<<1024, 256>>>(x, W_ft, W_conv, W1, W2);

    // feature transform + conv linear (applied per node; gather commutes)
    k_gemm<<<dim3(1, ROWB), 512, GSMEM>>>(pxc, pwft,   b_ft,   ph,  NNODES, FDIM, HDIM, 1, 1);
    k_gemm<<<dim3(1, ROWB), 512, GSMEM>>>(ph,  pwconv, b_conv, phw, NNODES, HDIM, HDIM, 0, 0);

    // edge pass 1: max distance + dst histogram
    k_distmax_hist<<<1024, 256>>>(ei, pos);
    // CSR offsets
    k_scan<<<1, 1024>>>();
    // edge pass 2: per-edge ab factors into CSR slots
    k_reorder<<<(NEDGES + 255) / 256, 256>>>(ei, pos, vf, vparams);
    // gather-aggregate per node (writes agg directly, no atomics)
    k_agg<<<1568, 256>>>();

    // BatchNorm: stats (coalesced) -> scale/shift -> apply (+relu+att+round)
    k_colstats<<<250, 512>>>();
    k_bnfinal<<<2, 256>>>(bn_gamma, bn_beta, att);
    k_bnact<<<8192, 256>>>();

    // MLP head: agg' @ W1^T -> LN+relu -> @ W2^T
    k_gemm<<<dim3(MID / 128, ROWB), 512, GSMEM>>>(pagg, pw1, b1, pz1, NNODES, ZDIM, MID, 0, 0);
    k_lnrelu<<<(NNODES + 7) / 8, 256>>>(ln_g, ln_b);
    k_gemm<<<dim3(ODIM / 128, ROWB), 512, GSMEM>>>(pz1, pw2, b2, out, NNODES, MID, ODIM, 0, 0);
}

// round 16
// speedup vs baseline: 1.0940x; 1.0007x over previous
#include <cuda_runtime.h>
#include <math.h>
#include <stdint.h>

#define NNODES 50000
#define NEDGES 800000
#define FDIM 128
#define HDIM 128
#define ODIM 128
#define KOBS 4
#define ZDIM 512   /* K*H */
#define MID  256   /* 2*H */

// ---------------- scratch (device globals; no allocation allowed) ----------
__device__ __align__(16) float g_xc [(size_t)NNODES * FDIM];   // tf32-rounded x
__device__ __align__(16) float g_h  [(size_t)NNODES * HDIM];
__device__ __align__(16) float g_hw [(size_t)NNODES * HDIM];
__device__ __align__(16) float g_agg[(size_t)NNODES * ZDIM];
__device__ __align__(16) float g_z1 [(size_t)NNODES * MID];
__device__ __align__(16) float g_wft  [HDIM * FDIM];
__device__ __align__(16) float g_wconv[HDIM * HDIM];
__device__ __align__(16) float g_w1   [MID * ZDIM];
__device__ __align__(16) float g_w2   [ODIM * MID];
__device__ double g_colsum  [ZDIM];
__device__ double g_colsumsq[ZDIM];
__device__ __align__(16) float g_scale[ZDIM];   // bn scale * attention
__device__ __align__(16) float g_shift[ZDIM];   // bn shift * attention
__device__ unsigned int g_distmax_bits;
// CSR structures
__device__ int g_cnt[NNODES];
__device__ int g_off[NNODES + 1];
__device__ int g_cur[NNODES];
__device__ int g_esrc[NEDGES];
__device__ __align__(16) float4 g_eab[NEDGES];

__device__ __forceinline__ float to_tf32(float x) {
    float r;
    asm("cvt.rna.tf32.f32 %0, %1;" : "=f"(r) : "f"(x));
    return r;
}

// ---------------- zero / init ----------------------------------------------
__global__ void k_zero_misc() {
    int i = blockIdx.x * blockDim.x + threadIdx.x;
    if (i == 0) g_distmax_bits = 0u;
    if (i < ZDIM) { g_colsum[i] = 0.0; g_colsumsq[i] = 0.0; }
    for (; i < NNODES; i += gridDim.x * blockDim.x) g_cnt[i] = 0;
}

// ---------------- single-launch tf32 rounding of all GEMM inputs ------------
__global__ void k_round_all(const float* __restrict__ x,
                            const float* __restrict__ wft,
                            const float* __restrict__ wconv,
                            const float* __restrict__ w1,
                            const float* __restrict__ w2)
{
    const int n0 = NNODES * FDIM / 4;
    const int n1 = HDIM * FDIM / 4;
    const int n2 = HDIM * HDIM / 4;
    const int n3 = MID * ZDIM / 4;
    const int n4 = ODIM * MID / 4;
    const int total = n0 + n1 + n2 + n3 + n4;
    int i = blockIdx.x * blockDim.x + threadIdx.x;
    for (; i < total; i += gridDim.x * blockDim.x) {
        const float4* s;
        float4* d;
        int j = i;
        if (j < n0)              { s = (const float4*)x;     d = (float4*)g_xc; }
        else if ((j -= n0) < n1) { s = (const float4*)wft;   d = (float4*)g_wft; }
        else if ((j -= n1) < n2) { s = (const float4*)wconv; d = (float4*)g_wconv; }
        else if ((j -= n2) < n3) { s = (const float4*)w1;    d = (float4*)g_w1; }
        else                     { j -= n3; s = (const float4*)w2; d = (float4*)g_w2; }
        float4 v = s[j];
        v.x = to_tf32(v.x); v.y = to_tf32(v.y);
        v.z = to_tf32(v.z); v.w = to_tf32(v.w);
        d[j] = v;
    }
}

// ---------------- tf32 tensor GEMM, cp.async 2-stage, 2 CTA/SM --------------
// C[r,c] = sum_k A[r,k] * W[c,k] + bias[c]   (A @ W^T + b)
// W must be PRE-ROUNDED to tf32. A pre-rounded unless amode==1.
// amode==1: A raw fp32; fragments transformed IN REGISTERS after LDS:
//           a' = tf32(relu(a*g_scale[k] + g_shift[k]))   (BN+relu+attention)
// 512 threads, tile 128x128, BK=32, 16 warps x (32x32).
#define GSM_STAGE 9216          /* floats per stage (A 4608 + W 4608) */
#define GSMEM     73728         /* bytes */

__global__ void __launch_bounds__(512, 2)
k_gemm(const float* __restrict__ A, const float* __restrict__ W,
       const float* __restrict__ bias, float* __restrict__ C,
       int nrows, int kdim, int mcols, int do_relu, int round_out, int amode)
{
    extern __shared__ float sm[];
    __shared__ float s_sc[ZDIM], s_sh[ZDIM];
    const int tid  = threadIdx.x;
    const int warp = tid >> 5;
    const int lane = tid & 31;
    const int row0 = blockIdx.y * 128;
    const int col0 = blockIdx.x * 128;
    const int mw = (warp & 3) * 32;
    const int nw = (warp >> 2) * 32;
    const int gq = lane >> 2;
    const int tq = lane & 3;
    const int r_ld = tid >> 3;           // 0..63
    const int kv   = (tid & 7) * 4;      // 0..28

    if (amode) {
        for (int c = tid; c < kdim; c += 512) {
            s_sc[c] = g_scale[c];
            s_sh[c] = g_shift[c];
        }
    }

    float acc[2][4][4];
#pragma unroll
    for (int mi = 0; mi < 2; mi++)
#pragma unroll
        for (int ni = 0; ni < 4; ni++)
#pragma unroll
            for (int q = 0; q < 4; q++) acc[mi][ni][q] = 0.f;

#define ISSUE(ST)                                                              \
    do {                                                                       \
        const int k0_ = (ST) * 32;                                             \
        float* dA_ = sm + ((ST) & 1) * GSM_STAGE;                              \
        _Pragma("unroll")                                                      \
        for (int t = 0; t < 2; t++) {                                          \
            int r = r_ld + t * 64;                                             \
            int ar = row0 + r; if (ar > nrows - 1) ar = nrows - 1;             \
            const float* sA = A + (size_t)ar * kdim + k0_ + kv;                \
            uint32_t du = (uint32_t)__cvta_generic_to_shared(dA_ + r * 36 + kv); \
            asm volatile("cp.async.cg.shared.global [%0], [%1], 16;"           \
                         :: "r"(du), "l"(sA));                                 \
            const float* sW = W + (size_t)(col0 + r) * kdim + k0_ + kv;        \
            uint32_t dw = (uint32_t)__cvta_generic_to_shared(dA_ + 4608 + r * 36 + kv); \
            asm volatile("cp.async.cg.shared.global [%0], [%1], 16;"           \
                         :: "r"(dw), "l"(sW));                                 \
        }                                                                      \
        asm volatile("cp.async.commit_group;" ::: "memory");                   \
    } while (0)

    const int nch = kdim >> 5;
    ISSUE(0);
    if (nch > 1) ISSUE(1);

    for (int i = 0; i < nch; i++) {
        if (i < nch - 1) asm volatile("cp.async.wait_group 1;" ::: "memory");
        else             asm volatile("cp.async.wait_group 0;" ::: "memory");
        __syncthreads();
        const float* As = sm + (i & 1) * GSM_STAGE;
        const float* Ws = As + 4608;
        const int k0 = i * 32;

#pragma unroll
        for (int j = 0; j < 4; j++) {
            const int kk = j * 8;
            uint32_t af[8], bf[8];
#pragma unroll
            for (int mi = 0; mi < 2; mi++) {
                int r = mw + mi * 16 + gq;
                af[mi * 4 + 0] = __float_as_uint(As[r * 36 + kk + tq]);
                af[mi * 4 + 1] = __float_as_uint(As[(r + 8) * 36 + kk + tq]);
                af[mi * 4 + 2] = __float_as_uint(As[r * 36 + kk + tq + 4]);
                af[mi * 4 + 3] = __float_as_uint(As[(r + 8) * 36 + kk + tq + 4]);
            }
            if (amode) {
                // columns: c0 = k0+kk+tq (af[.0], af[.1]), c1 = c0+4 (af[.2], af[.3])
                float sc0 = s_sc[k0 + kk + tq],     sh0 = s_sh[k0 + kk + tq];
                float sc1 = s_sc[k0 + kk + tq + 4], sh1 = s_sh[k0 + kk + tq + 4];
#pragma unroll
                for (int mi = 0; mi < 2; mi++) {
                    float a0 = __uint_as_float(af[mi * 4 + 0]);
                    float a1 = __uint_as_float(af[mi * 4 + 1]);
                    float a2 = __uint_as_float(af[mi * 4 + 2]);
                    float a3 = __uint_as_float(af[mi * 4 + 3]);
                    af[mi * 4 + 0] = __float_as_uint(to_tf32(fmaxf(fmaf(a0, sc0, sh0), 0.f)));
                    af[mi * 4 + 1] = __float_as_uint(to_tf32(fmaxf(fmaf(a1, sc0, sh0), 0.f)));
                    af[mi * 4 + 2] = __float_as_uint(to_tf32(fmaxf(fmaf(a2, sc1, sh1), 0.f)));
                    af[mi * 4 + 3] = __float_as_uint(to_tf32(fmaxf(fmaf(a3, sc1, sh1), 0.f)));
                }
            }
#pragma unroll
            for (int ni = 0; ni < 4; ni++) {
                int cc = nw + ni * 8 + gq;
                bf[ni * 2 + 0] = __float_as_uint(Ws[cc * 36 + kk + tq]);
                bf[ni * 2 + 1] = __float_as_uint(Ws[cc * 36 + kk + tq + 4]);
            }
#pragma unroll
            for (int mi = 0; mi < 2; mi++)
#pragma unroll
                for (int ni = 0; ni < 4; ni++) {
                    asm volatile(
                        "mma.sync.aligned.m16n8k8.row.col.f32.tf32.tf32.f32 "
                        "{%0,%1,%2,%3}, {%4,%5,%6,%7}, {%8,%9}, {%0,%1,%2,%3};"
                        : "+f"(acc[mi][ni][0]), "+f"(acc[mi][ni][1]),
                          "+f"(acc[mi][ni][2]), "+f"(acc[mi][ni][3])
                        : "r"(af[mi * 4 + 0]), "r"(af[mi * 4 + 1]),
                          "r"(af[mi * 4 + 2]), "r"(af[mi * 4 + 3]),
                          "r"(bf[ni * 2 + 0]), "r"(bf[ni * 2 + 1]));
                }
        }
        __syncthreads();
        if (i + 2 < nch) ISSUE(i + 2);
    }

    // ---- epilogue: bias (+ optional relu, optional tf32 rounding) ----
#pragma unroll
    for (int mi = 0; mi < 2; mi++) {
        int r0 = row0 + mw + mi * 16 + gq;
#pragma unroll
        for (int ni = 0; ni < 4; ni++) {
            int ccol = col0 + nw + ni * 8 + tq * 2;
            float b0 = bias[ccol], b1 = bias[ccol + 1];
            float v0 = acc[mi][ni][0] + b0;
            float v1 = acc[mi][ni][1] + b1;
            float v2 = acc[mi][ni][2] + b0;
            float v3 = acc[mi][ni][3] + b1;
            if (do_relu) {
                v0 = fmaxf(v0, 0.f); v1 = fmaxf(v1, 0.f);
                v2 = fmaxf(v2, 0.f); v3 = fmaxf(v3, 0.f);
            }
            if (round_out) {
                v0 = to_tf32(v0); v1 = to_tf32(v1);
                v2 = to_tf32(v2); v3 = to_tf32(v3);
            }
            if (r0 < nrows)
                *(float2*)&C[(size_t)r0 * mcols + ccol] = make_float2(v0, v1);
            if (r0 + 8 < nrows)
                *(float2*)&C[(size_t)(r0 + 8) * mcols + ccol] = make_float2(v2, v3);
        }
    }
}

// ---------------- pass 1 over edges: max distance + dst histogram -----------
__global__ void k_distmax_hist(const int* __restrict__ ei, const float* __restrict__ pos)
{
    int i = blockIdx.x * blockDim.x + threadIdx.x;
    float m = 0.f;
    for (; i < NEDGES; i += gridDim.x * blockDim.x) {
        int s = ei[i], d = ei[NEDGES + i];
        float ax = pos[3 * s + 0] - pos[3 * d + 0];
        float ay = pos[3 * s + 1] - pos[3 * d + 1];
        float az = pos[3 * s + 2] - pos[3 * d + 2];
        m = fmaxf(m, sqrtf(ax * ax + ay * ay + az * az));
        atomicAdd(&g_cnt[d], 1);
    }
#pragma unroll
    for (int o = 16; o; o >>= 1) m = fmaxf(m, __shfl_xor_sync(0xffffffffu, m, o));
    if ((threadIdx.x & 31) == 0) atomicMax(&g_distmax_bits, __float_as_uint(m));
}

// ---------------- exclusive scan of g_cnt -> g_off, g_cur (one block) -------
__global__ void __launch_bounds__(1024) k_scan()
{
    const int CH = (NNODES + 1023) / 1024;   // 49
    __shared__ int wsum[32];
    int t = threadIdx.x;
    int lane = t & 31, wid = t >> 5;
    int base = t * CH;

    int s = 0;
#pragma unroll 4
    for (int i = 0; i < CH; i++) {
        int idx = base + i;
        if (idx < NNODES) s += g_cnt[idx];
    }
    int incl = s;
#pragma unroll
    for (int o = 1; o < 32; o <<= 1) {
        int v = __shfl_up_sync(0xffffffffu, incl, o);
        if (lane >= o) incl += v;
    }
    if (lane == 31) wsum[wid] = incl;
    __syncthreads();
    if (wid == 0) {
        int w = wsum[lane];
        int wi = w;
#pragma unroll
        for (int o = 1; o < 32; o <<= 1) {
            int v = __shfl_up_sync(0xffffffffu, wi, o);
            if (lane >= o) wi += v;
        }
        wsum[lane] = wi - w;   // exclusive warp offsets
    }
    __syncthreads();
    int excl = wsum[wid] + incl - s;
    int run = excl;
    for (int i = 0; i < CH; i++) {
        int idx = base + i;
        if (idx < NNODES) {
            g_off[idx] = run;
            g_cur[idx] = run;
            run += g_cnt[idx];
        }
    }
    if (t == 1023) g_off[NNODES] = NEDGES;
}

// ---------------- pass 2: compute ab[4] per edge, place into CSR order ------
__global__ void k_reorder(const int* __restrict__ ei, const float* __restrict__ pos,
                          const float* __restrict__ vfp, const float* __restrict__ vparams)
{
    int e = blockIdx.x * blockDim.x + threadIdx.x;
    if (e >= NEDGES) return;
    int s = __ldg(&ei[e]);
    int d = __ldg(&ei[NEDGES + e]);

    float ax = pos[3 * s + 0] - pos[3 * d + 0];
    float ay = pos[3 * s + 1] - pos[3 * d + 1];
    float az = pos[3 * s + 2] - pos[3 * d + 2];
    float dist = sqrtf(ax * ax + ay * ay + az * az);
    float dmax = __uint_as_float(g_distmax_bits);
    float r    = dist / dmax;
    float inv  = 1.f / (dist + 1e-8f);
    float dsum = (ax + ay + az) * inv;
    float vf   = vfp[0];

    float4 ab;
    {
        float v, g2;
        v = vf * fminf(r, vparams[0]); g2 = 1.f - v * v + 1e-8f;
        ab.x = sqrtf(g2) / (1.f + v * dsum);
        v = vf * fminf(r, vparams[1]); g2 = 1.f - v * v + 1e-8f;
        ab.y = sqrtf(g2) / (1.f + v * dsum);
        v = vf * fminf(r, vparams[2]); g2 = 1.f - v * v + 1e-8f;
        ab.z = sqrtf(g2) / (1.f + v * dsum);
        v = vf * fminf(r, vparams[3]); g2 = 1.f - v * v + 1e-8f;
        ab.w = sqrtf(g2) / (1.f + v * dsum);
    }
    int p = atomicAdd(&g_cur[d], 1);
    g_esrc[p] = s;
    g_eab[p]  = ab;
}

// ---------------- aggregate: one warp per node (no stats fusion) -------------
#define ACCUM(AB, HV)                                                        \
    do {                                                                     \
        acc[ 0] = fmaf(AB.x, HV.x, acc[ 0]); acc[ 1] = fmaf(AB.x, HV.y, acc[ 1]); \
        acc[ 2] = fmaf(AB.x, HV.z, acc[ 2]); acc[ 3] = fmaf(AB.x, HV.w, acc[ 3]); \
        acc[ 4] = fmaf(AB.y, HV.x, acc[ 4]); acc[ 5] = fmaf(AB.y, HV.y, acc[ 5]); \
        acc[ 6] = fmaf(AB.y, HV.z, acc[ 6]); acc[ 7] = fmaf(AB.y, HV.w, acc[ 7]); \
        acc[ 8] = fmaf(AB.z, HV.x, acc[ 8]); acc[ 9] = fmaf(AB.z, HV.y, acc[ 9]); \
        acc[10] = fmaf(AB.z, HV.z, acc[10]); acc[11] = fmaf(AB.z, HV.w, acc[11]); \
        acc[12] = fmaf(AB.w, HV.x, acc[12]); acc[13] = fmaf(AB.w, HV.y, acc[13]); \
        acc[14] = fmaf(AB.w, HV.z, acc[14]); acc[15] = fmaf(AB.w, HV.w, acc[15]); \
    } while (0)

__global__ void __launch_bounds__(256)
k_agg()
{
    const int lane = threadIdx.x & 31;
    const int wid  = (blockIdx.x << 3) + (threadIdx.x >> 5);
    const int nwarps = gridDim.x << 3;
    const float* __restrict__ hw = g_hw;
    const int*   __restrict__ esrc = g_esrc;
    const float4* __restrict__ eab = g_eab;

    for (int node = wid; node < NNODES; node += nwarps) {
        float acc[16];
#pragma unroll
        for (int i = 0; i < 16; i++) acc[i] = 0.f;
        const int p0 = g_off[node], p1 = g_off[node + 1];
        int p = p0;
        for (; p + 4 <= p1; p += 4) {
            int s0 = esrc[p + 0], s1 = esrc[p + 1];
            int s2 = esrc[p + 2], s3 = esrc[p + 3];
            float4 ab0 = eab[p + 0], ab1 = eab[p + 1];
            float4 ab2 = eab[p + 2], ab3 = eab[p + 3];
            float4 h0 = *(const float4*)&hw[(size_t)s0 * HDIM + lane * 4];
            float4 h1 = *(const float4*)&hw[(size_t)s1 * HDIM + lane * 4];
            float4 h2 = *(const float4*)&hw[(size_t)s2 * HDIM + lane * 4];
            float4 h3 = *(const float4*)&hw[(size_t)s3 * HDIM + lane * 4];
            ACCUM(ab0, h0);
            ACCUM(ab1, h1);
            ACCUM(ab2, h2);
            ACCUM(ab3, h3);
        }
        for (; p < p1; p++) {
            int s = esrc[p];
            float4 ab = eab[p];
            float4 h = *(const float4*)&hw[(size_t)s * HDIM + lane * 4];
            ACCUM(ab, h);
        }
        float* op = &g_agg[(size_t)node * ZDIM + lane * 4];
        *(float4*)(op + 0 * HDIM) = make_float4(acc[ 0], acc[ 1], acc[ 2], acc[ 3]);
        *(float4*)(op + 1 * HDIM) = make_float4(acc[ 4], acc[ 5], acc[ 6], acc[ 7]);
        *(float4*)(op + 2 * HDIM) = make_float4(acc[ 8], acc[ 9], acc[10], acc[11]);
        *(float4*)(op + 3 * HDIM) = make_float4(acc[12], acc[13], acc[14], acc[15]);
    }
}

// ---------------- BN column stats, coalesced (thread = column) --------------
__global__ void __launch_bounds__(512) k_colstats()
{
    const int c  = threadIdx.x;              // column 0..511
    const int r0 = blockIdx.x * 200;         // grid.x = 250
    int r1 = r0 + 200; if (r1 > NNODES) r1 = NNODES;
    float s = 0.f, s2 = 0.f;
    const float* p = g_agg + (size_t)r0 * ZDIM + c;
#pragma unroll 4
    for (int r = r0; r < r1; r++, p += ZDIM) {
        float v = *p;
        s += v; s2 = fmaf(v, v, s2);
    }
    atomicAdd(&g_colsum[c],   (double)s);
    atomicAdd(&g_colsumsq[c], (double)s2);
}

__global__ void k_bnfinal(const float* __restrict__ bn_gamma,
                          const float* __restrict__ bn_beta,
                          const float* __restrict__ att)
{
    int c = blockIdx.x * blockDim.x + threadIdx.x;
    if (c >= ZDIM) return;
    float mean = (float)(g_colsum[c] * (1.0 / NNODES));
    float var  = (float)(g_colsumsq[c] * (1.0 / NNODES)) - mean * mean;
    float invs = 1.f / sqrtf(var + 1e-5f);
    float a  = att[c];                      // attention >= 0: fold through relu
    float sc = invs * bn_gamma[c];
    g_scale[c] = sc * a;
    g_shift[c] = (bn_beta[c] - mean * sc) * a;
}

// ---------------- LayerNorm (per row of z1 [N,256]) + relu + round ----------
__global__ void k_lnrelu(const float* __restrict__ gam, const float* __restrict__ bet)
{
    int row = blockIdx.x * (blockDim.x >> 5) + (threadIdx.x >> 5);
    if (row >= NNODES) return;
    int lane = threadIdx.x & 31;
    float* p = g_z1 + (size_t)row * MID;
    float v[8];
    float s = 0.f;
#pragma unroll
    for (int i = 0; i < 8; i++) { v[i] = p[lane + 32 * i]; s += v[i]; }
#pragma unroll
    for (int o = 16; o; o >>= 1) s += __shfl_xor_sync(0xffffffffu, s, o);
    float mean = s * (1.f / MID);
    float q = 0.f;
#pragma unroll
    for (int i = 0; i < 8; i++) { float t = v[i] - mean; q += t * t; }
#pragma unroll
    for (int o = 16; o; o >>= 1) q += __shfl_xor_sync(0xffffffffu, q, o);
    float inv = rsqrtf(q * (1.f / MID) + 1e-5f);
#pragma unroll
    for (int i = 0; i < 8; i++) {
        int c = lane + 32 * i;
        p[c] = to_tf32(fmaxf((v[i] - mean) * inv * gam[c] + bet[c], 0.f));
    }
}

// ---------------- launch -----------------------------------------------------
extern "C" void kernel_launch(void* const* d_in, const int* in_sizes, int n_in,
                              void* d_out, int out_size)
{
    const float* x        = (const float*)d_in[0];
    const int*   ei       = (const int*)  d_in[1];
    const float* pos      = (const float*)d_in[2];
    const float* W_ft     = (const float*)d_in[3];
    const float* b_ft     = (const float*)d_in[4];
    const float* W_conv   = (const float*)d_in[5];
    const float* b_conv   = (const float*)d_in[6];
    const float* vf       = (const float*)d_in[7];
    const float* vparams  = (const float*)d_in[8];
    const float* bn_gamma = (const float*)d_in[9];
    const float* bn_beta  = (const float*)d_in[10];
    const float* att      = (const float*)d_in[11];
    const float* W1       = (const float*)d_in[12];
    const float* b1       = (const float*)d_in[13];
    const float* ln_g     = (const float*)d_in[14];
    const float* ln_b     = (const float*)d_in[15];
    const float* W2       = (const float*)d_in[16];
    const float* b2       = (const float*)d_in[17];
    float* out = (float*)d_out;

    float *pxc, *ph, *phw, *pagg, *pz1, *pwft, *pwconv, *pw1, *pw2;
    cudaGetSymbolAddress((void**)&pxc,   g_xc);
    cudaGetSymbolAddress((void**)&ph,    g_h);
    cudaGetSymbolAddress((void**)&phw,   g_hw);
    cudaGetSymbolAddress((void**)&pagg,  g_agg);
    cudaGetSymbolAddress((void**)&pz1,   g_z1);
    cudaGetSymbolAddress((void**)&pwft,  g_wft);
    cudaGetSymbolAddress((void**)&pwconv,g_wconv);
    cudaGetSymbolAddress((void**)&pw1,   g_w1);
    cudaGetSymbolAddress((void**)&pw2,   g_w2);

    cudaFuncSetAttribute(k_gemm, cudaFuncAttributeMaxDynamicSharedMemorySize, GSMEM);

    const int ROWB = (NNODES + 127) / 128;  // 391

    // init counters
    k_zero_misc<<<64, 1024>>>();

    // tf32-round ALL GEMM inputs in one launch
    k_round_all<<<1024, 256>>>(x, W_ft, W_conv, W1, W2);

    // feature transform + conv linear (applied per node; gather commutes)
    k_gemm<<<dim3(1, ROWB), 512, GSMEM>>>(pxc, pwft,   b_ft,   ph,  NNODES, FDIM, HDIM, 1, 1, 0);
    k_gemm<<<dim3(1, ROWB), 512, GSMEM>>>(ph,  pwconv, b_conv, phw, NNODES, HDIM, HDIM, 0, 0, 0);

    // edge pass 1: max distance + dst histogram
    k_distmax_hist<<<1024, 256>>>(ei, pos);
    // CSR offsets
    k_scan<<<1, 1024>>>();
    // edge pass 2: per-edge ab factors into CSR slots
    k_reorder<<<(NEDGES + 255) / 256, 256>>>(ei, pos, vf, vparams);
    // gather-aggregate per node (writes agg directly, no atomics)
    k_agg<<<1568, 256>>>();

    // BatchNorm: stats (coalesced) -> scale/shift; transform fused into W1 GEMM
    k_colstats<<<250, 512>>>();
    k_bnfinal<<<2, 256>>>(bn_gamma, bn_beta, att);

    // MLP head: relu(BN(agg))*att (in-register in GEMM) @ W1^T -> LN+relu -> @ W2^T
    k_gemm<<<dim3(MID / 128, ROWB), 512, GSMEM>>>(pagg, pw1, b1, pz1, NNODES, ZDIM, MID, 0, 0, 1);
    k_lnrelu<<<(NNODES + 7) / 8, 256>>>(ln_g, ln_b);
    k_gemm<<<dim3(ODIM / 128, ROWB), 512, GSMEM>>>(pz1, pw2, b2, out, NNODES, MID, ODIM, 0, 0, 0);
}